// round 13
// baseline (speedup 1.0000x reference)
#include <cuda_runtime.h>
#include <cuda_bf16.h>
#include <cstdint>

// ---------------------------------------------------------------------------
// GaussianNNHeightmapEncoder — R13
//   R12 + concurrency: both HMMA kernels resized for 2 CTAs/SM.
//   gauss: 4 samples/CTA, 256 thr, 112 KB smem (W0 via __ldg)
//   compress: M=64 tile, 320 thr, 100 KB smem, grid 256 (one wave on 296 slots)
// ---------------------------------------------------------------------------

#define MAXB 16384

__device__ float g_K[4 * 64 * 64];
__device__ __nv_bfloat16 g_hi[(size_t)MAXB * 4096];
__device__ __nv_bfloat16 g_lo[(size_t)MAXB * 4096];
__device__ __nv_bfloat16 g_w0hi[80 * 4096];
__device__ __nv_bfloat16 g_w0lo[80 * 4096];

__device__ __forceinline__ float lrelu(float v) { return fmaxf(v, 0.01f * v); }

__device__ __forceinline__ uint32_t smem_u32(const void* p) {
    uint32_t a;
    asm("{ .reg .u64 t; cvta.to.shared.u64 t, %1; cvt.u32.u64 %0, t; }" : "=r"(a) : "l"(p));
    return a;
}

__device__ __forceinline__ void split_bf16(float v, __nv_bfloat16& h, __nv_bfloat16& l) {
    h = __float2bfloat16(v);
    l = __float2bfloat16(v - __bfloat162float(h));
}
__device__ __forceinline__ void split2(float v0, float v1, uint32_t& hi, uint32_t& lo) {
    __nv_bfloat16 h0, l0, h1, l1;
    split_bf16(v0, h0, l0);
    split_bf16(v1, h1, l1);
    __nv_bfloat162 H, L;
    H.x = h0; H.y = h1;
    L.x = l0; L.y = l1;
    hi = *(uint32_t*)&H;
    lo = *(uint32_t*)&L;
}

// ---- async copy / ldmatrix / mma helpers ----
__device__ __forceinline__ void cp16(uint32_t dst, const void* src, int sz) {
    asm volatile("cp.async.cg.shared.global [%0], [%1], 16, %2;"
                 :: "r"(dst), "l"(src), "r"(sz) : "memory");
}
__device__ __forceinline__ void cp_commit() {
    asm volatile("cp.async.commit_group;" ::: "memory");
}
template <int N>
__device__ __forceinline__ void cp_wait() {
    asm volatile("cp.async.wait_group %0;" :: "n"(N) : "memory");
}
__device__ __forceinline__ void ldsm4(uint32_t* r, uint32_t addr) {
    asm volatile("ldmatrix.sync.aligned.m8n8.x4.shared.b16 {%0,%1,%2,%3}, [%4];"
                 : "=r"(r[0]), "=r"(r[1]), "=r"(r[2]), "=r"(r[3]) : "r"(addr));
}
__device__ __forceinline__ void mma16816(float* d, const uint32_t* a, const uint32_t* b) {
    asm volatile(
        "mma.sync.aligned.m16n8k16.row.col.f32.bf16.bf16.f32 "
        "{%0,%1,%2,%3}, {%4,%5,%6,%7}, {%8,%9}, {%0,%1,%2,%3};"
        : "+f"(d[0]), "+f"(d[1]), "+f"(d[2]), "+f"(d[3])
        : "r"(a[0]), "r"(a[1]), "r"(a[2]), "r"(a[3]), "r"(b[0]), "r"(b[1]));
}

// ---------------------------------------------------------------------------
// Kernel P: normalized Gaussian kernels (4 x 64 x 64)
// ---------------------------------------------------------------------------
__global__ void kprep_kernel(const float* __restrict__ s0, const float* __restrict__ s1,
                             const float* __restrict__ s2, const float* __restrict__ s3) {
    int tid = threadIdx.x;
    if (tid >= 256) return;
    int l = tid >> 6, i = tid & 63;
    float sig = (l == 0) ? s0[0] : (l == 1) ? s1[0] : (l == 2) ? s2[0] : s3[0];
    float inv = 1.0f / (2.0f * sig * sig);
    float e[64];
    float sum = 0.0f;
#pragma unroll 8
    for (int j = 0; j < 64; j++) {
        float d = (float)(i - j);
        e[j] = __expf(-d * d * inv);
        sum += e[j];
    }
    float r = 1.0f / fmaxf(sum, 1e-12f);
    float* dst = g_K + (l * 64 + i) * 64;
#pragma unroll 8
    for (int j = 0; j < 64; j++) dst[j] = e[j] * r;
}

// ---------------------------------------------------------------------------
// Kernel W: split wm0 (80x4096 fp32) into bf16 hi/lo
// ---------------------------------------------------------------------------
__global__ void wprep_kernel(const float* __restrict__ wm0) {
    int idx = blockIdx.x * 512 + threadIdx.x;
    if (idx >= 81920) return;
    float4 v = *(const float4*)(wm0 + (size_t)idx * 4);
    __nv_bfloat16 h[4], l[4];
    split_bf16(v.x, h[0], l[0]);
    split_bf16(v.y, h[1], l[1]);
    split_bf16(v.z, h[2], l[2]);
    split_bf16(v.w, h[3], l[3]);
    *(uint2*)(g_w0hi + (size_t)idx * 4) = *(uint2*)h;
    *(uint2*)(g_w0lo + (size_t)idx * 4) = *(uint2*)l;
}

// ---------------------------------------------------------------------------
// gauss_mma smem layout (bytes) — 4 samples / CTA, 256 threads
//   KA:  K hi/lo [64][72] bf16 (144 B rows)
//   W:   W1(rows 0-15) W2(16-47) W3(48-111), [.][40] bf16 (80 B rows)
//   RM:  state row-major [256][40] bf16   (row = s*64+i)
//   CM:  state chan-major [128][72] bf16  (row = s*C+c)
// ---------------------------------------------------------------------------
#define GS_B0    0
#define GS_B1    32
#define GS_B2    96
#define GS_B3    224
#define GS_KA_HI 512
#define GS_KA_LO 9728
#define GS_W_HI  18944
#define GS_W_LO  27904
#define GS_RM_HI 36864
#define GS_RM_LO 57344
#define GS_CM_HI 77824
#define GS_CM_LO 96256
#define GS_SMEM  114688

__device__ __forceinline__ void stage_Kl(char* smem, int l, int tid) {
    const float* __restrict__ src = g_K + l * 4096;
    for (int t = tid; t < 4096; t += 256) {
        int i = t >> 6, j = t & 63;
        __nv_bfloat16 h, lo;
        split_bf16(src[t], h, lo);
        *(__nv_bfloat16*)(smem + GS_KA_HI + ((i * 72 + j) << 1)) = h;
        *(__nv_bfloat16*)(smem + GS_KA_LO + ((i * 72 + j) << 1)) = lo;
    }
}

// K-mul: D[64 x 4C] = K @ CM^T ; -> CM (lrelu, L0) or RM (pre-act)
template <int C, bool TO_CM>
__device__ __forceinline__ void kmul_mma(char* smem, uint32_t sb, int lane, int w) {
    constexpr int CH = C / 4;
    constexpr int SH = (C == 8) ? 3 : (C == 16) ? 4 : 5;
    int mt = w & 3;
    int n0t = (w >> 2) * CH;                        // (w>>2) in {0,1}
    int g = lane >> 3;
    float acc[CH][4];
#pragma unroll
    for (int t = 0; t < CH; t++)
#pragma unroll
        for (int e = 0; e < 4; e++) acc[t][e] = 0.0f;

    uint32_t arow0 = (uint32_t)(mt * 16 + (lane & 15)) * 144 + (uint32_t)(lane >> 4) * 16;
#pragma unroll
    for (int ks = 0; ks < 4; ks++) {
        uint32_t ahi[4], alo[4];
        uint32_t ao = arow0 + ks * 32;
        ldsm4(ahi, sb + GS_KA_HI + ao);
        ldsm4(alo, sb + GS_KA_LO + ao);
#pragma unroll
        for (int p = 0; p < CH / 2; p++) {
            uint32_t brow = (uint32_t)((n0t + p * 2) * 8 + (g >> 1) * 8 + (lane & 7)) * 144
                          + (uint32_t)(g & 1) * 16 + ks * 32;
            uint32_t bhi[4], blo[4];
            ldsm4(bhi, sb + GS_CM_HI + brow);
            ldsm4(blo, sb + GS_CM_LO + brow);
            mma16816(acc[p * 2],     ahi, bhi);
            mma16816(acc[p * 2 + 1], ahi, bhi + 2);
            mma16816(acc[p * 2],     alo, bhi);
            mma16816(acc[p * 2 + 1], alo, bhi + 2);
            mma16816(acc[p * 2],     ahi, blo);
            mma16816(acc[p * 2 + 1], ahi, blo + 2);
        }
    }
    if (TO_CM) __syncthreads();
    int r0 = mt * 16 + (lane >> 2);
    int cp = (lane & 3) * 2;
#pragma unroll
    for (int t = 0; t < CH; t++) {
        int nn = (n0t + t) * 8 + cp;
#pragma unroll
        for (int h2 = 0; h2 < 2; h2++) {
            int i = r0 + h2 * 8;
            float v0 = acc[t][h2 * 2 + 0], v1 = acc[t][h2 * 2 + 1];
            if (TO_CM) {
                v0 = lrelu(v0); v1 = lrelu(v1);
                __nv_bfloat16 h0, l0, h1, l1;
                split_bf16(v0, h0, l0);
                split_bf16(v1, h1, l1);
                *(__nv_bfloat16*)(smem + GS_CM_HI + (((nn    ) * 72 + i) << 1)) = h0;
                *(__nv_bfloat16*)(smem + GS_CM_HI + (((nn + 1) * 72 + i) << 1)) = h1;
                *(__nv_bfloat16*)(smem + GS_CM_LO + (((nn    ) * 72 + i) << 1)) = l0;
                *(__nv_bfloat16*)(smem + GS_CM_LO + (((nn + 1) * 72 + i) << 1)) = l1;
            } else {
                int s = nn >> SH, c = nn & (C - 1);
                uint32_t off = (((uint32_t)(s * 64 + i) * 40 + c) << 1);
                uint32_t hi, lo;
                split2(v0, v1, hi, lo);
                *(uint32_t*)(smem + GS_RM_HI + off) = hi;
                *(uint32_t*)(smem + GS_RM_LO + off) = lo;
            }
        }
    }
}

// W-mul: D[256 x Cout] = RM @ W^T (+bias, lrelu); -> CM (L1,2) or gmem (L3)
template <int CIN, int COUT, int L>
__device__ __forceinline__ void wmul_mma(char* smem, uint32_t sb, int lane, int w,
                                         const float* __restrict__ bias,
                                         long bbase, int Bn) {
    constexpr int KS = (CIN + 15) / 16;
    constexpr int NT = COUT / 8;
    constexpr int NC = (NT < 4) ? NT : 4;
    constexpr int NCH = NT / NC;
    constexpr int WROW = (L == 1) ? 0 : (L == 2) ? 16 : 48;
    int mt0 = w * 2;
    int g = lane >> 3;
    int r0 = (lane >> 2);
    int cp = (lane & 3) * 2;
#pragma unroll
    for (int ch = 0; ch < NCH; ch++) {
        float acc[2][NC][4];
#pragma unroll
        for (int m = 0; m < 2; m++)
#pragma unroll
            for (int t = 0; t < NC; t++)
#pragma unroll
                for (int e = 0; e < 4; e++) acc[m][t][e] = 0.0f;
#pragma unroll
        for (int ks = 0; ks < KS; ks++) {
            uint32_t ahi[2][4], alo[2][4];
#pragma unroll
            for (int m = 0; m < 2; m++) {
                uint32_t ao = (uint32_t)((mt0 + m) * 16 + (lane & 15)) * 80
                            + (uint32_t)(lane >> 4) * 16 + ks * 32;
                ldsm4(ahi[m], sb + GS_RM_HI + ao);
                ldsm4(alo[m], sb + GS_RM_LO + ao);
            }
#pragma unroll
            for (int p = 0; p < NC / 2; p++) {
                uint32_t brow = (uint32_t)(WROW + (ch * NC + p * 2) * 8 + (g >> 1) * 8 + (lane & 7)) * 80
                              + (uint32_t)(g & 1) * 16 + ks * 32;
                uint32_t bhi[4], blo[4];
                ldsm4(bhi, sb + GS_W_HI + brow);
                ldsm4(blo, sb + GS_W_LO + brow);
#pragma unroll
                for (int m = 0; m < 2; m++) {
                    mma16816(acc[m][p * 2],     ahi[m], bhi);
                    mma16816(acc[m][p * 2 + 1], ahi[m], bhi + 2);
                    mma16816(acc[m][p * 2],     alo[m], bhi);
                    mma16816(acc[m][p * 2 + 1], alo[m], bhi + 2);
                    mma16816(acc[m][p * 2],     ahi[m], blo);
                    mma16816(acc[m][p * 2 + 1], ahi[m], blo + 2);
                }
            }
        }
#pragma unroll
        for (int m = 0; m < 2; m++) {
#pragma unroll
            for (int t = 0; t < NC; t++) {
                int o = (ch * NC + t) * 8 + cp;
                float b0v = bias[o], b1v = bias[o + 1];
#pragma unroll
                for (int h2 = 0; h2 < 2; h2++) {
                    int mg = (mt0 + m) * 16 + r0 + h2 * 8;
                    int s = mg >> 6, i = mg & 63;
                    float v0 = lrelu(acc[m][t][h2 * 2 + 0] + b0v);
                    float v1 = lrelu(acc[m][t][h2 * 2 + 1] + b1v);
                    if (L < 3) {
                        int row = s * COUT + o;
                        __nv_bfloat16 h0, l0, h1, l1;
                        split_bf16(v0, h0, l0);
                        split_bf16(v1, h1, l1);
                        *(__nv_bfloat16*)(smem + GS_CM_HI + (((row    ) * 72 + i) << 1)) = h0;
                        *(__nv_bfloat16*)(smem + GS_CM_HI + (((row + 1) * 72 + i) << 1)) = h1;
                        *(__nv_bfloat16*)(smem + GS_CM_LO + (((row    ) * 72 + i) << 1)) = l0;
                        *(__nv_bfloat16*)(smem + GS_CM_LO + (((row + 1) * 72 + i) << 1)) = l1;
                    } else {
                        long bb = bbase + s;
                        if (bb < Bn) {
                            uint32_t hi, lo;
                            split2(v0, v1, hi, lo);
                            size_t word = ((size_t)bb * 4096 + (size_t)i * 64 + o) >> 1;
                            ((uint32_t*)g_hi)[word] = hi;
                            ((uint32_t*)g_lo)[word] = lo;
                        }
                    }
                }
            }
        }
    }
}

__global__ __launch_bounds__(256, 2) void gauss_mma_kernel(
    const float* __restrict__ x,
    const float* __restrict__ w0, const float* __restrict__ b0,
    const float* __restrict__ w1, const float* __restrict__ b1,
    const float* __restrict__ w2, const float* __restrict__ b2,
    const float* __restrict__ w3, const float* __restrict__ b3,
    int B) {
    extern __shared__ char smem[];
    uint32_t sb = smem_u32(smem);
    int tid = threadIdx.x, lane = tid & 31, w = tid >> 5;

    // zero W region (k-padding) and RM (c-padding for L1's k16 step)
    for (int t = tid; t < 4480; t += 256) ((uint32_t*)(smem + GS_W_HI))[t] = 0u;
    for (int t = tid; t < 10240; t += 256) ((uint32_t*)(smem + GS_RM_HI))[t] = 0u;
    __syncthreads();

    if (tid < 8)  ((float*)(smem + GS_B0))[tid] = b0[tid];
    if (tid < 16) ((float*)(smem + GS_B1))[tid] = b1[tid];
    if (tid < 32) ((float*)(smem + GS_B2))[tid] = b2[tid];
    if (tid < 64) ((float*)(smem + GS_B3))[tid] = b3[tid];
    for (int t = tid; t < 128; t += 256) {          // W1 [16][8] -> rows 0..15
        int o = t >> 3, c = t & 7;
        __nv_bfloat16 h, l;
        split_bf16(w1[t], h, l);
        *(__nv_bfloat16*)(smem + GS_W_HI + ((o * 40 + c) << 1)) = h;
        *(__nv_bfloat16*)(smem + GS_W_LO + ((o * 40 + c) << 1)) = l;
    }
    for (int t = tid; t < 512; t += 256) {          // W2 [32][16] -> rows 16..47
        int o = t >> 4, c = t & 15;
        __nv_bfloat16 h, l;
        split_bf16(w2[t], h, l);
        *(__nv_bfloat16*)(smem + GS_W_HI + (((16 + o) * 40 + c) << 1)) = h;
        *(__nv_bfloat16*)(smem + GS_W_LO + (((16 + o) * 40 + c) << 1)) = l;
    }
    for (int t = tid; t < 2048; t += 256) {         // W3 [64][32] -> rows 48..111
        int o = t >> 5, c = t & 31;
        __nv_bfloat16 h, l;
        split_bf16(w3[t], h, l);
        *(__nv_bfloat16*)(smem + GS_W_HI + (((48 + o) * 40 + c) << 1)) = h;
        *(__nv_bfloat16*)(smem + GS_W_LO + (((48 + o) * 40 + c) << 1)) = l;
    }
    stage_Kl(smem, 0, tid);
    __syncthreads();

    // ---- L0 (FFMA, w0 via __ldg): XP = X @ W0^T + b0 -> CM[(s*8+o)][i]
    {
        int s = tid >> 6, i = tid & 63;
        long b = (long)blockIdx.x * 4 + s;
        bool act = (b < B);
        const float* xrow = x + (act ? b * 4096 + (long)i * 64 : 0);
        const float* b0s = (const float*)(smem + GS_B0);
        float acc[8];
#pragma unroll
        for (int o = 0; o < 8; o++) acc[o] = b0s[o];
#pragma unroll
        for (int half = 0; half < 2; half++) {
            float4 xr[8];
#pragma unroll
            for (int q = 0; q < 8; q++)
                xr[q] = act ? *(const float4*)&xrow[half * 32 + q * 4]
                            : make_float4(0.f, 0.f, 0.f, 0.f);
#pragma unroll
            for (int o = 0; o < 8; o++) {
#pragma unroll
                for (int q = 0; q < 8; q++) {
                    float4 wv = __ldg((const float4*)&w0[o * 64 + half * 32 + q * 4]);
                    acc[o] = fmaf(xr[q].x, wv.x, fmaf(xr[q].y, wv.y,
                             fmaf(xr[q].z, wv.z, fmaf(xr[q].w, wv.w, acc[o]))));
                }
            }
        }
#pragma unroll
        for (int o = 0; o < 8; o++) {
            __nv_bfloat16 h, l;
            split_bf16(acc[o], h, l);
            *(__nv_bfloat16*)(smem + GS_CM_HI + (((s * 8 + o) * 72 + i) << 1)) = h;
            *(__nv_bfloat16*)(smem + GS_CM_LO + (((s * 8 + o) * 72 + i) << 1)) = l;
        }
    }
    __syncthreads();

    const float* b1s = (const float*)(smem + GS_B1);
    const float* b2s = (const float*)(smem + GS_B2);
    const float* b3s = (const float*)(smem + GS_B3);
    long bbase = (long)blockIdx.x * 4;

    kmul_mma<8, true>(smem, sb, lane, w);           // K0 @ XP, lrelu -> CM (in-place)
    stage_Kl(smem, 1, tid);
    __syncthreads();

    kmul_mma<8, false>(smem, sb, lane, w);          // K1 @ h -> RM
    __syncthreads();
    wmul_mma<8, 16, 1>(smem, sb, lane, w, b1s, bbase, B);   // -> CM
    stage_Kl(smem, 2, tid);
    __syncthreads();

    kmul_mma<16, false>(smem, sb, lane, w);         // K2 @ h -> RM
    __syncthreads();
    wmul_mma<16, 32, 2>(smem, sb, lane, w, b2s, bbase, B);  // -> CM
    stage_Kl(smem, 3, tid);
    __syncthreads();

    kmul_mma<32, false>(smem, sb, lane, w);         // K3 @ h -> RM
    __syncthreads();
    wmul_mma<32, 64, 3>(smem, sb, lane, w, b3s, bbase, B);  // -> g_hi/g_lo
}

// ---------------------------------------------------------------------------
// Kernel C (HMMA): M=64 tile, 320 threads (10 warps = 2Mx5N), 2 CTAs/SM.
// ---------------------------------------------------------------------------
#define C2_SW1    0
#define C2_STG0   19456
#define C2_A_HI   0
#define C2_A_LO   9216
#define C2_B_HI   18432
#define C2_B_LO   29952
#define C2_STG_SZ 41472
#define C2_SMEM   (C2_STG0 + 2 * C2_STG_SZ)        // 102400

__global__ __launch_bounds__(320, 2) void compress_mma_kernel(
    const float* __restrict__ bm0, const float* __restrict__ wm1,
    const float* __restrict__ bm1, float* __restrict__ out, int B) {
    extern __shared__ char smem[];
    uint32_t sb = smem_u32(smem);
    int tid = threadIdx.x;
    long m0 = (long)blockIdx.x * 64;

    float* sW1 = (float*)(smem + C2_SW1);
    for (int t = tid; t < 4800; t += 320) sW1[t] = wm1[t];

    int lane = tid & 31, w = tid >> 5;
    int nw = (w < 5) ? w : w - 5;
    int mw = (w < 5) ? 0 : 1;
    int g = lane >> 3;

    auto load_chunk = [&](int c, int bsel) {
        uint32_t stg = sb + C2_STG0 + bsel * C2_STG_SZ;
        int k0 = c * 64;
        for (int q = tid; q < 512; q += 320) {
            int m = q >> 3, kk = q & 7;
            long gm = m0 + m;
            int ok = (gm < B);
            size_t off = (size_t)(ok ? gm : 0) * 4096 + k0 + kk * 8;
            int sz = ok ? 16 : 0;
            uint32_t d = stg + m * 144 + kk * 16;
            cp16(d + C2_A_HI, g_hi + off, sz);
            cp16(d + C2_A_LO, g_lo + off, sz);
        }
        for (int q = tid; q < 640; q += 320) {
            int o = q >> 3, kk = q & 7;
            size_t off = (size_t)o * 4096 + k0 + kk * 8;
            uint32_t d = stg + o * 144 + kk * 16;
            cp16(d + C2_B_HI, g_w0hi + off, 16);
            cp16(d + C2_B_LO, g_w0lo + off, 16);
        }
        cp_commit();
    };

    float acc[2][2][4];
#pragma unroll
    for (int mt = 0; mt < 2; mt++)
#pragma unroll
        for (int nt = 0; nt < 2; nt++)
#pragma unroll
            for (int e = 0; e < 4; e++) acc[mt][nt][e] = 0.0f;

    load_chunk(0, 0);
    load_chunk(1, 1);

    uint32_t aoff0 = (uint32_t)(mw * 32 + (lane & 15)) * 144 + (uint32_t)(lane >> 4) * 16;
    uint32_t boff0 = (uint32_t)(nw * 16 + (g >> 1) * 8 + (lane & 7)) * 144 + (uint32_t)(g & 1) * 16;

#pragma unroll 1
    for (int c = 0; c < 64; c++) {
        int bsel = c & 1;
        cp_wait<1>();
        __syncthreads();
        uint32_t stg = sb + C2_STG0 + bsel * C2_STG_SZ;

#pragma unroll
        for (int ks = 0; ks < 4; ks++) {
            uint32_t ahi[2][4], alo[2][4], bhi[4], blo[4];
            uint32_t ao = stg + aoff0 + ks * 32;
            ldsm4(ahi[0], ao + C2_A_HI);
            ldsm4(ahi[1], ao + C2_A_HI + 16 * 144);
            ldsm4(alo[0], ao + C2_A_LO);
            ldsm4(alo[1], ao + C2_A_LO + 16 * 144);
            uint32_t bo = stg + boff0 + ks * 32;
            ldsm4(bhi, bo + C2_B_HI);
            ldsm4(blo, bo + C2_B_LO);
#pragma unroll
            for (int mt = 0; mt < 2; mt++)
#pragma unroll
                for (int nt = 0; nt < 2; nt++) {
                    mma16816(acc[mt][nt], ahi[mt], bhi + nt * 2);
                    mma16816(acc[mt][nt], alo[mt], bhi + nt * 2);
                    mma16816(acc[mt][nt], ahi[mt], blo + nt * 2);
                }
        }
        __syncthreads();
        if (c + 2 < 64) load_chunk(c + 2, bsel);
        else cp_commit();
    }

    // Epilogue: acc -> +bm0 -> lrelu -> h1[64][81] (overlays stage area)
    float* h1 = (float*)(smem + C2_STG0);
    int qrow = lane >> 2;
    int qcol = (lane & 3) * 2;
#pragma unroll
    for (int mt = 0; mt < 2; mt++)
#pragma unroll
        for (int i = 0; i < 2; i++) {
            int r = mw * 32 + mt * 16 + qrow + i * 8;
#pragma unroll
            for (int nt = 0; nt < 2; nt++)
#pragma unroll
                for (int j = 0; j < 2; j++) {
                    int col = nw * 16 + nt * 8 + qcol + j;
                    h1[r * 81 + col] = lrelu(acc[mt][nt][i * 2 + j] + __ldg(&bm0[col]));
                }
        }
    __syncthreads();

    // Second layer: 64 rows x 60 outs = 3840 outputs over 320 threads.
#pragma unroll 1
    for (int ii = 0; ii < 12; ii++) {
        int idx = tid + ii * 320;
        int m = idx & 63, o2 = idx >> 6;
        float a = __ldg(&bm1[o2]);
#pragma unroll 4
        for (int c4 = 0; c4 < 80; c4 += 4) {
            float4 wv = *(const float4*)&sW1[o2 * 80 + c4];
            a = fmaf(h1[m * 81 + c4 + 0], wv.x,
                fmaf(h1[m * 81 + c4 + 1], wv.y,
                fmaf(h1[m * 81 + c4 + 2], wv.z,
                fmaf(h1[m * 81 + c4 + 3], wv.w, a))));
        }
        long gm = m0 + m;
        if (gm < B) out[gm * 60 + o2] = lrelu(a);
    }
}

// ---------------------------------------------------------------------------
extern "C" void kernel_launch(void* const* d_in, const int* in_sizes, int n_in,
                              void* d_out, int out_size) {
    const float* x   = (const float*)d_in[0];
    const float* w0  = (const float*)d_in[1];
    const float* b0  = (const float*)d_in[2];
    const float* s0  = (const float*)d_in[3];
    const float* w1  = (const float*)d_in[4];
    const float* b1  = (const float*)d_in[5];
    const float* s1  = (const float*)d_in[6];
    const float* w2  = (const float*)d_in[7];
    const float* b2  = (const float*)d_in[8];
    const float* s2  = (const float*)d_in[9];
    const float* w3  = (const float*)d_in[10];
    const float* b3  = (const float*)d_in[11];
    const float* s3  = (const float*)d_in[12];
    const float* wm0 = (const float*)d_in[13];
    const float* bm0 = (const float*)d_in[14];
    const float* wm1 = (const float*)d_in[15];
    const float* bm1 = (const float*)d_in[16];

    int B = in_sizes[0] / 4096;
    if (B > MAXB) B = MAXB;

    cudaFuncSetAttribute((const void*)gauss_mma_kernel,
                         cudaFuncAttributeMaxDynamicSharedMemorySize, GS_SMEM);
    cudaFuncSetAttribute((const void*)compress_mma_kernel,
                         cudaFuncAttributeMaxDynamicSharedMemorySize, C2_SMEM);

    kprep_kernel<<<1, 256>>>(s0, s1, s2, s3);
    wprep_kernel<<<160, 512>>>(wm0);
    gauss_mma_kernel<<<(B + 3) / 4, 256, GS_SMEM>>>(
        x, w0, b0, w1, b1, w2, b2, w3, b3, B);
    compress_mma_kernel<<<(B + 63) / 64, 320, C2_SMEM>>>(
        bm0, wm1, bm1, (float*)d_out, B);
}

// round 14
// speedup vs baseline: 1.2908x; 1.2908x over previous
#include <cuda_runtime.h>
#include <cuda_bf16.h>
#include <cstdint>

// ---------------------------------------------------------------------------
// GaussianNNHeightmapEncoder — R14
//   gauss: R12 shape (8 samples/CTA, 512 thr) + presplit K in gmem +
//          cp.async double-buffered K prefetch (staging off critical path)
//   compress: R13 version (M=64 tile, 320 thr, 2 CTAs/SM) — measured 135.7 us
// ---------------------------------------------------------------------------

#define MAXB 16384

__device__ __nv_bfloat16 g_Khi[4 * 64 * 72];       // padded rows (144 B)
__device__ __nv_bfloat16 g_Klo[4 * 64 * 72];
__device__ __nv_bfloat16 g_hi[(size_t)MAXB * 4096];
__device__ __nv_bfloat16 g_lo[(size_t)MAXB * 4096];
__device__ __nv_bfloat16 g_w0hi[80 * 4096];
__device__ __nv_bfloat16 g_w0lo[80 * 4096];

__device__ __forceinline__ float lrelu(float v) { return fmaxf(v, 0.01f * v); }

__device__ __forceinline__ uint32_t smem_u32(const void* p) {
    uint32_t a;
    asm("{ .reg .u64 t; cvta.to.shared.u64 t, %1; cvt.u32.u64 %0, t; }" : "=r"(a) : "l"(p));
    return a;
}

__device__ __forceinline__ void split_bf16(float v, __nv_bfloat16& h, __nv_bfloat16& l) {
    h = __float2bfloat16(v);
    l = __float2bfloat16(v - __bfloat162float(h));
}
__device__ __forceinline__ void split2(float v0, float v1, uint32_t& hi, uint32_t& lo) {
    __nv_bfloat16 h0, l0, h1, l1;
    split_bf16(v0, h0, l0);
    split_bf16(v1, h1, l1);
    __nv_bfloat162 H, L;
    H.x = h0; H.y = h1;
    L.x = l0; L.y = l1;
    hi = *(uint32_t*)&H;
    lo = *(uint32_t*)&L;
}

// ---- async copy / ldmatrix / mma helpers ----
__device__ __forceinline__ void cp16(uint32_t dst, const void* src, int sz) {
    asm volatile("cp.async.cg.shared.global [%0], [%1], 16, %2;"
                 :: "r"(dst), "l"(src), "r"(sz) : "memory");
}
__device__ __forceinline__ void cp_commit() {
    asm volatile("cp.async.commit_group;" ::: "memory");
}
template <int N>
__device__ __forceinline__ void cp_wait() {
    asm volatile("cp.async.wait_group %0;" :: "n"(N) : "memory");
}
__device__ __forceinline__ void ldsm4(uint32_t* r, uint32_t addr) {
    asm volatile("ldmatrix.sync.aligned.m8n8.x4.shared.b16 {%0,%1,%2,%3}, [%4];"
                 : "=r"(r[0]), "=r"(r[1]), "=r"(r[2]), "=r"(r[3]) : "r"(addr));
}
__device__ __forceinline__ void mma16816(float* d, const uint32_t* a, const uint32_t* b) {
    asm volatile(
        "mma.sync.aligned.m16n8k16.row.col.f32.bf16.bf16.f32 "
        "{%0,%1,%2,%3}, {%4,%5,%6,%7}, {%8,%9}, {%0,%1,%2,%3};"
        : "+f"(d[0]), "+f"(d[1]), "+f"(d[2]), "+f"(d[3])
        : "r"(a[0]), "r"(a[1]), "r"(a[2]), "r"(a[3]), "r"(b[0]), "r"(b[1]));
}

// ---------------------------------------------------------------------------
// Kernel P: normalized Gaussian kernels, presplit hi/lo into padded gmem
// ---------------------------------------------------------------------------
__global__ void kprep_kernel(const float* __restrict__ s0, const float* __restrict__ s1,
                             const float* __restrict__ s2, const float* __restrict__ s3) {
    int tid = threadIdx.x;
    if (tid >= 256) return;
    int l = tid >> 6, i = tid & 63;
    float sig = (l == 0) ? s0[0] : (l == 1) ? s1[0] : (l == 2) ? s2[0] : s3[0];
    float inv = 1.0f / (2.0f * sig * sig);
    float e[64];
    float sum = 0.0f;
#pragma unroll 8
    for (int j = 0; j < 64; j++) {
        float d = (float)(i - j);
        e[j] = __expf(-d * d * inv);
        sum += e[j];
    }
    float r = 1.0f / fmaxf(sum, 1e-12f);
    __nv_bfloat16* dh = g_Khi + (l * 64 + i) * 72;
    __nv_bfloat16* dl = g_Klo + (l * 64 + i) * 72;
#pragma unroll 8
    for (int j = 0; j < 64; j++) {
        __nv_bfloat16 h, lo;
        split_bf16(e[j] * r, h, lo);
        dh[j] = h; dl[j] = lo;
    }
#pragma unroll
    for (int j = 64; j < 72; j++) { dh[j] = __float2bfloat16(0.f); dl[j] = __float2bfloat16(0.f); }
}

// ---------------------------------------------------------------------------
// Kernel W: split wm0 (80x4096 fp32) into bf16 hi/lo
// ---------------------------------------------------------------------------
__global__ void wprep_kernel(const float* __restrict__ wm0) {
    int idx = blockIdx.x * 512 + threadIdx.x;
    if (idx >= 81920) return;
    float4 v = *(const float4*)(wm0 + (size_t)idx * 4);
    __nv_bfloat16 h[4], l[4];
    split_bf16(v.x, h[0], l[0]);
    split_bf16(v.y, h[1], l[1]);
    split_bf16(v.z, h[2], l[2]);
    split_bf16(v.w, h[3], l[3]);
    *(uint2*)(g_w0hi + (size_t)idx * 4) = *(uint2*)h;
    *(uint2*)(g_w0lo + (size_t)idx * 4) = *(uint2*)l;
}

// ---------------------------------------------------------------------------
// gauss_mma smem layout (bytes) — 8 samples / CTA, 512 threads
//   KA0/KA1: double-buffered K hi/lo [64][72] bf16 (144 B rows)
//   W:   W1(rows 0-15) W2(16-47) W3(48-111), [.][40] bf16 (80 B rows)
//   RM:  state row-major [512][40] bf16
//   CM:  state chan-major [256][72] bf16
// ---------------------------------------------------------------------------
#define GM_W0F    0
#define GM_B0F    2048
#define GM_B1F    2080
#define GM_B2F    2144
#define GM_B3F    2272
#define GM_KA0_HI 2560
#define GM_KA0_LO 11776
#define GM_KA1_HI 20992
#define GM_KA1_LO 30208
#define GM_W_HI   39424
#define GM_W_LO   48384
#define GM_RM_HI  57344
#define GM_RM_LO  98304
#define GM_CM_HI  139264
#define GM_CM_LO  176128
#define GM_SMEM   212992

// async-stage one layer's presplit K into a KA buffer (576 x 16B per half)
__device__ __forceinline__ void stage_K_cp(uint32_t sb, int l, int tid,
                                           uint32_t dhi, uint32_t dlo) {
    const char* srch = (const char*)(g_Khi + l * 4608);
    const char* srcl = (const char*)(g_Klo + l * 4608);
    for (int t = tid; t < 576; t += 512) {
        cp16(sb + dhi + t * 16, srch + t * 16, 16);
        cp16(sb + dlo + t * 16, srcl + t * 16, 16);
    }
    cp_commit();
}

// K-mul: D[64 x 8C] = K @ CM^T ; -> CM (lrelu, L0) or RM (pre-act)
template <int C, bool TO_CM>
__device__ __forceinline__ void kmul_mma(char* smem, uint32_t sb, int lane, int w,
                                         uint32_t ka_hi, uint32_t ka_lo) {
    constexpr int CH = C / 4;
    constexpr int SH = (C == 8) ? 3 : (C == 16) ? 4 : 5;
    int mt = w & 3;
    int n0t = (w >> 2) * CH;
    int g = lane >> 3;
    float acc[CH][4];
#pragma unroll
    for (int t = 0; t < CH; t++)
#pragma unroll
        for (int e = 0; e < 4; e++) acc[t][e] = 0.0f;

    uint32_t arow0 = (uint32_t)(mt * 16 + (lane & 15)) * 144 + (uint32_t)(lane >> 4) * 16;
#pragma unroll
    for (int ks = 0; ks < 4; ks++) {
        uint32_t ahi[4], alo[4];
        uint32_t ao = arow0 + ks * 32;
        ldsm4(ahi, sb + ka_hi + ao);
        ldsm4(alo, sb + ka_lo + ao);
#pragma unroll
        for (int p = 0; p < CH / 2; p++) {
            uint32_t brow = (uint32_t)((n0t + p * 2) * 8 + (g >> 1) * 8 + (lane & 7)) * 144
                          + (uint32_t)(g & 1) * 16 + ks * 32;
            uint32_t bhi[4], blo[4];
            ldsm4(bhi, sb + GM_CM_HI + brow);
            ldsm4(blo, sb + GM_CM_LO + brow);
            mma16816(acc[p * 2],     ahi, bhi);
            mma16816(acc[p * 2 + 1], ahi, bhi + 2);
            mma16816(acc[p * 2],     alo, bhi);
            mma16816(acc[p * 2 + 1], alo, bhi + 2);
            mma16816(acc[p * 2],     ahi, blo);
            mma16816(acc[p * 2 + 1], ahi, blo + 2);
        }
    }
    if (TO_CM) __syncthreads();
    int r0 = mt * 16 + (lane >> 2);
    int cp = (lane & 3) * 2;
#pragma unroll
    for (int t = 0; t < CH; t++) {
        int nn = (n0t + t) * 8 + cp;
#pragma unroll
        for (int h2 = 0; h2 < 2; h2++) {
            int i = r0 + h2 * 8;
            float v0 = acc[t][h2 * 2 + 0], v1 = acc[t][h2 * 2 + 1];
            if (TO_CM) {
                v0 = lrelu(v0); v1 = lrelu(v1);
                __nv_bfloat16 h0, l0, h1, l1;
                split_bf16(v0, h0, l0);
                split_bf16(v1, h1, l1);
                *(__nv_bfloat16*)(smem + GM_CM_HI + (((nn    ) * 72 + i) << 1)) = h0;
                *(__nv_bfloat16*)(smem + GM_CM_HI + (((nn + 1) * 72 + i) << 1)) = h1;
                *(__nv_bfloat16*)(smem + GM_CM_LO + (((nn    ) * 72 + i) << 1)) = l0;
                *(__nv_bfloat16*)(smem + GM_CM_LO + (((nn + 1) * 72 + i) << 1)) = l1;
            } else {
                int s = nn >> SH, c = nn & (C - 1);
                uint32_t off = (((uint32_t)(s * 64 + i) * 40 + c) << 1);
                uint32_t hi, lo;
                split2(v0, v1, hi, lo);
                *(uint32_t*)(smem + GM_RM_HI + off) = hi;
                *(uint32_t*)(smem + GM_RM_LO + off) = lo;
            }
        }
    }
}

// W-mul: D[512 x Cout] = RM @ W^T (+bias, lrelu); -> CM (L1,2) or gmem (L3)
template <int CIN, int COUT, int L>
__device__ __forceinline__ void wmul_mma(char* smem, uint32_t sb, int lane, int w,
                                         const float* __restrict__ bias,
                                         long bbase, int Bn) {
    constexpr int KS = (CIN + 15) / 16;
    constexpr int NT = COUT / 8;
    constexpr int NC = (NT < 4) ? NT : 4;
    constexpr int NCH = NT / NC;
    constexpr int WROW = (L == 1) ? 0 : (L == 2) ? 16 : 48;
    int mt0 = w * 2;
    int g = lane >> 3;
    int r0 = (lane >> 2);
    int cp = (lane & 3) * 2;
#pragma unroll
    for (int ch = 0; ch < NCH; ch++) {
        float acc[2][NC][4];
#pragma unroll
        for (int m = 0; m < 2; m++)
#pragma unroll
            for (int t = 0; t < NC; t++)
#pragma unroll
                for (int e = 0; e < 4; e++) acc[m][t][e] = 0.0f;
#pragma unroll
        for (int ks = 0; ks < KS; ks++) {
            uint32_t ahi[2][4], alo[2][4];
#pragma unroll
            for (int m = 0; m < 2; m++) {
                uint32_t ao = (uint32_t)((mt0 + m) * 16 + (lane & 15)) * 80
                            + (uint32_t)(lane >> 4) * 16 + ks * 32;
                ldsm4(ahi[m], sb + GM_RM_HI + ao);
                ldsm4(alo[m], sb + GM_RM_LO + ao);
            }
#pragma unroll
            for (int p = 0; p < NC / 2; p++) {
                uint32_t brow = (uint32_t)(WROW + (ch * NC + p * 2) * 8 + (g >> 1) * 8 + (lane & 7)) * 80
                              + (uint32_t)(g & 1) * 16 + ks * 32;
                uint32_t bhi[4], blo[4];
                ldsm4(bhi, sb + GM_W_HI + brow);
                ldsm4(blo, sb + GM_W_LO + brow);
#pragma unroll
                for (int m = 0; m < 2; m++) {
                    mma16816(acc[m][p * 2],     ahi[m], bhi);
                    mma16816(acc[m][p * 2 + 1], ahi[m], bhi + 2);
                    mma16816(acc[m][p * 2],     alo[m], bhi);
                    mma16816(acc[m][p * 2 + 1], alo[m], bhi + 2);
                    mma16816(acc[m][p * 2],     ahi[m], blo);
                    mma16816(acc[m][p * 2 + 1], ahi[m], blo + 2);
                }
            }
        }
#pragma unroll
        for (int m = 0; m < 2; m++) {
#pragma unroll
            for (int t = 0; t < NC; t++) {
                int o = (ch * NC + t) * 8 + cp;
                float b0v = bias[o], b1v = bias[o + 1];
#pragma unroll
                for (int h2 = 0; h2 < 2; h2++) {
                    int mg = (mt0 + m) * 16 + r0 + h2 * 8;
                    int s = mg >> 6, i = mg & 63;
                    float v0 = lrelu(acc[m][t][h2 * 2 + 0] + b0v);
                    float v1 = lrelu(acc[m][t][h2 * 2 + 1] + b1v);
                    if (L < 3) {
                        int row = s * COUT + o;
                        __nv_bfloat16 h0, l0, h1, l1;
                        split_bf16(v0, h0, l0);
                        split_bf16(v1, h1, l1);
                        *(__nv_bfloat16*)(smem + GM_CM_HI + (((row    ) * 72 + i) << 1)) = h0;
                        *(__nv_bfloat16*)(smem + GM_CM_HI + (((row + 1) * 72 + i) << 1)) = h1;
                        *(__nv_bfloat16*)(smem + GM_CM_LO + (((row    ) * 72 + i) << 1)) = l0;
                        *(__nv_bfloat16*)(smem + GM_CM_LO + (((row + 1) * 72 + i) << 1)) = l1;
                    } else {
                        long bb = bbase + s;
                        if (bb < Bn) {
                            uint32_t hi, lo;
                            split2(v0, v1, hi, lo);
                            size_t word = ((size_t)bb * 4096 + (size_t)i * 64 + o) >> 1;
                            ((uint32_t*)g_hi)[word] = hi;
                            ((uint32_t*)g_lo)[word] = lo;
                        }
                    }
                }
            }
        }
    }
}

__global__ __launch_bounds__(512, 1) void gauss_mma_kernel(
    const float* __restrict__ x,
    const float* __restrict__ w0, const float* __restrict__ b0,
    const float* __restrict__ w1, const float* __restrict__ b1,
    const float* __restrict__ w2, const float* __restrict__ b2,
    const float* __restrict__ w3, const float* __restrict__ b3,
    int B) {
    extern __shared__ char smem[];
    uint32_t sb = smem_u32(smem);
    int tid = threadIdx.x, lane = tid & 31, w = tid >> 5;

    // K0 prefetch starts immediately (group 0)
    stage_K_cp(sb, 0, tid, GM_KA0_HI, GM_KA0_LO);

    // zero W region (k-padding) and RM (c-padding for L1's k16 step)
    for (int t = tid; t < 4480; t += 512) ((uint32_t*)(smem + GM_W_HI))[t] = 0u;
    for (int t = tid; t < 20480; t += 512) ((uint32_t*)(smem + GM_RM_HI))[t] = 0u;
    __syncthreads();

    // stage constants
    float* W0s = (float*)(smem + GM_W0F);
    for (int t = tid; t < 512; t += 512) W0s[t] = w0[t];
    if (tid < 8)  ((float*)(smem + GM_B0F))[tid] = b0[tid];
    if (tid < 16) ((float*)(smem + GM_B1F))[tid] = b1[tid];
    if (tid < 32) ((float*)(smem + GM_B2F))[tid] = b2[tid];
    if (tid < 64) ((float*)(smem + GM_B3F))[tid] = b3[tid];
    for (int t = tid; t < 128; t += 512) {          // W1 [16][8] -> rows 0..15
        int o = t >> 3, c = t & 7;
        __nv_bfloat16 h, l;
        split_bf16(w1[t], h, l);
        *(__nv_bfloat16*)(smem + GM_W_HI + ((o * 40 + c) << 1)) = h;
        *(__nv_bfloat16*)(smem + GM_W_LO + ((o * 40 + c) << 1)) = l;
    }
    for (int t = tid; t < 512; t += 512) {          // W2 [32][16] -> rows 16..47
        int o = t >> 4, c = t & 15;
        __nv_bfloat16 h, l;
        split_bf16(w2[t], h, l);
        *(__nv_bfloat16*)(smem + GM_W_HI + (((16 + o) * 40 + c) << 1)) = h;
        *(__nv_bfloat16*)(smem + GM_W_LO + (((16 + o) * 40 + c) << 1)) = l;
    }
    for (int t = tid; t < 2048; t += 512) {         // W3 [64][32] -> rows 48..111
        int o = t >> 5, c = t & 31;
        __nv_bfloat16 h, l;
        split_bf16(w3[t], h, l);
        *(__nv_bfloat16*)(smem + GM_W_HI + (((48 + o) * 40 + c) << 1)) = h;
        *(__nv_bfloat16*)(smem + GM_W_LO + (((48 + o) * 40 + c) << 1)) = l;
    }

    // ---- L0 (FFMA): XP = X @ W0^T + b0 -> CM[(s*8+o)][i]
    {
        int s = tid >> 6, i = tid & 63;
        long b = (long)blockIdx.x * 8 + s;
        bool act = (b < B);
        const float* xrow = x + (act ? b * 4096 + (long)i * 64 : 0);
        const float* b0s = (const float*)(smem + GM_B0F);
        float acc[8];
#pragma unroll
        for (int o = 0; o < 8; o++) acc[o] = b0s[o];
#pragma unroll
        for (int half = 0; half < 2; half++) {
            float4 xr[8];
#pragma unroll
            for (int q = 0; q < 8; q++)
                xr[q] = act ? *(const float4*)&xrow[half * 32 + q * 4]
                            : make_float4(0.f, 0.f, 0.f, 0.f);
#pragma unroll
            for (int o = 0; o < 8; o++) {
#pragma unroll
                for (int q = 0; q < 8; q++) {
                    float4 wv = *(const float4*)&W0s[o * 64 + half * 32 + q * 4];
                    acc[o] = fmaf(xr[q].x, wv.x, fmaf(xr[q].y, wv.y,
                             fmaf(xr[q].z, wv.z, fmaf(xr[q].w, wv.w, acc[o]))));
                }
            }
        }
#pragma unroll
        for (int o = 0; o < 8; o++) {
            __nv_bfloat16 h, l;
            split_bf16(acc[o], h, l);
            *(__nv_bfloat16*)(smem + GM_CM_HI + (((s * 8 + o) * 72 + i) << 1)) = h;
            *(__nv_bfloat16*)(smem + GM_CM_LO + (((s * 8 + o) * 72 + i) << 1)) = l;
        }
    }
    cp_wait<0>();                                    // K0 arrived
    __syncthreads();

    const float* b1s = (const float*)(smem + GM_B1F);
    const float* b2s = (const float*)(smem + GM_B2F);
    const float* b3s = (const float*)(smem + GM_B3F);
    long bbase = (long)blockIdx.x * 8;

    stage_K_cp(sb, 1, tid, GM_KA1_HI, GM_KA1_LO);    // prefetch K1 during kmul0
    kmul_mma<8, true>(smem, sb, lane, w, GM_KA0_HI, GM_KA0_LO);  // CM in-place
    cp_wait<0>();
    __syncthreads();

    stage_K_cp(sb, 2, tid, GM_KA0_HI, GM_KA0_LO);    // prefetch K2 during kmul1
    kmul_mma<8, false>(smem, sb, lane, w, GM_KA1_HI, GM_KA1_LO); // -> RM
    cp_wait<0>();
    __syncthreads();
    wmul_mma<8, 16, 1>(smem, sb, lane, w, b1s, bbase, B);        // -> CM
    __syncthreads();

    stage_K_cp(sb, 3, tid, GM_KA1_HI, GM_KA1_LO);    // prefetch K3 during kmul2
    kmul_mma<16, false>(smem, sb, lane, w, GM_KA0_HI, GM_KA0_LO); // -> RM
    cp_wait<0>();
    __syncthreads();
    wmul_mma<16, 32, 2>(smem, sb, lane, w, b2s, bbase, B);       // -> CM
    __syncthreads();

    kmul_mma<32, false>(smem, sb, lane, w, GM_KA1_HI, GM_KA1_LO); // -> RM
    __syncthreads();
    wmul_mma<32, 64, 3>(smem, sb, lane, w, b3s, bbase, B);       // -> g_hi/g_lo
}

// ---------------------------------------------------------------------------
// Kernel C (HMMA): M=64 tile, 320 threads (10 warps = 2Mx5N), 2 CTAs/SM.
// ---------------------------------------------------------------------------
#define C2_SW1    0
#define C2_STG0   19456
#define C2_A_HI   0
#define C2_A_LO   9216
#define C2_B_HI   18432
#define C2_B_LO   29952
#define C2_STG_SZ 41472
#define C2_SMEM   (C2_STG0 + 2 * C2_STG_SZ)        // 102400

__global__ __launch_bounds__(320, 2) void compress_mma_kernel(
    const float* __restrict__ bm0, const float* __restrict__ wm1,
    const float* __restrict__ bm1, float* __restrict__ out, int B) {
    extern __shared__ char smem[];
    uint32_t sb = smem_u32(smem);
    int tid = threadIdx.x;
    long m0 = (long)blockIdx.x * 64;

    float* sW1 = (float*)(smem + C2_SW1);
    for (int t = tid; t < 4800; t += 320) sW1[t] = wm1[t];

    int lane = tid & 31, w = tid >> 5;
    int nw = (w < 5) ? w : w - 5;
    int mw = (w < 5) ? 0 : 1;
    int g = lane >> 3;

    auto load_chunk = [&](int c, int bsel) {
        uint32_t stg = sb + C2_STG0 + bsel * C2_STG_SZ;
        int k0 = c * 64;
        for (int q = tid; q < 512; q += 320) {
            int m = q >> 3, kk = q & 7;
            long gm = m0 + m;
            int ok = (gm < B);
            size_t off = (size_t)(ok ? gm : 0) * 4096 + k0 + kk * 8;
            int sz = ok ? 16 : 0;
            uint32_t d = stg + m * 144 + kk * 16;
            cp16(d + C2_A_HI, g_hi + off, sz);
            cp16(d + C2_A_LO, g_lo + off, sz);
        }
        for (int q = tid; q < 640; q += 320) {
            int o = q >> 3, kk = q & 7;
            size_t off = (size_t)o * 4096 + k0 + kk * 8;
            uint32_t d = stg + o * 144 + kk * 16;
            cp16(d + C2_B_HI, g_w0hi + off, 16);
            cp16(d + C2_B_LO, g_w0lo + off, 16);
        }
        cp_commit();
    };

    float acc[2][2][4];
#pragma unroll
    for (int mt = 0; mt < 2; mt++)
#pragma unroll
        for (int nt = 0; nt < 2; nt++)
#pragma unroll
            for (int e = 0; e < 4; e++) acc[mt][nt][e] = 0.0f;

    load_chunk(0, 0);
    load_chunk(1, 1);

    uint32_t aoff0 = (uint32_t)(mw * 32 + (lane & 15)) * 144 + (uint32_t)(lane >> 4) * 16;
    uint32_t boff0 = (uint32_t)(nw * 16 + (g >> 1) * 8 + (lane & 7)) * 144 + (uint32_t)(g & 1) * 16;

#pragma unroll 1
    for (int c = 0; c < 64; c++) {
        int bsel = c & 1;
        cp_wait<1>();
        __syncthreads();
        uint32_t stg = sb + C2_STG0 + bsel * C2_STG_SZ;

#pragma unroll
        for (int ks = 0; ks < 4; ks++) {
            uint32_t ahi[2][4], alo[2][4], bhi[4], blo[4];
            uint32_t ao = stg + aoff0 + ks * 32;
            ldsm4(ahi[0], ao + C2_A_HI);
            ldsm4(ahi[1], ao + C2_A_HI + 16 * 144);
            ldsm4(alo[0], ao + C2_A_LO);
            ldsm4(alo[1], ao + C2_A_LO + 16 * 144);
            uint32_t bo = stg + boff0 + ks * 32;
            ldsm4(bhi, bo + C2_B_HI);
            ldsm4(blo, bo + C2_B_LO);
#pragma unroll
            for (int mt = 0; mt < 2; mt++)
#pragma unroll
                for (int nt = 0; nt < 2; nt++) {
                    mma16816(acc[mt][nt], ahi[mt], bhi + nt * 2);
                    mma16816(acc[mt][nt], alo[mt], bhi + nt * 2);
                    mma16816(acc[mt][nt], ahi[mt], blo + nt * 2);
                }
        }
        __syncthreads();
        if (c + 2 < 64) load_chunk(c + 2, bsel);
        else cp_commit();
    }

    // Epilogue: acc -> +bm0 -> lrelu -> h1[64][81] (overlays stage area)
    float* h1 = (float*)(smem + C2_STG0);
    int qrow = lane >> 2;
    int qcol = (lane & 3) * 2;
#pragma unroll
    for (int mt = 0; mt < 2; mt++)
#pragma unroll
        for (int i = 0; i < 2; i++) {
            int r = mw * 32 + mt * 16 + qrow + i * 8;
#pragma unroll
            for (int nt = 0; nt < 2; nt++)
#pragma unroll
                for (int j = 0; j < 2; j++) {
                    int col = nw * 16 + nt * 8 + qcol + j;
                    h1[r * 81 + col] = lrelu(acc[mt][nt][i * 2 + j] + __ldg(&bm0[col]));
                }
        }
    __syncthreads();

    // Second layer: 64 rows x 60 outs = 3840 outputs over 320 threads.
#pragma unroll 1
    for (int ii = 0; ii < 12; ii++) {
        int idx = tid + ii * 320;
        int m = idx & 63, o2 = idx >> 6;
        float a = __ldg(&bm1[o2]);
#pragma unroll 4
        for (int c4 = 0; c4 < 80; c4 += 4) {
            float4 wv = *(const float4*)&sW1[o2 * 80 + c4];
            a = fmaf(h1[m * 81 + c4 + 0], wv.x,
                fmaf(h1[m * 81 + c4 + 1], wv.y,
                fmaf(h1[m * 81 + c4 + 2], wv.z,
                fmaf(h1[m * 81 + c4 + 3], wv.w, a))));
        }
        long gm = m0 + m;
        if (gm < B) out[gm * 60 + o2] = lrelu(a);
    }
}

// ---------------------------------------------------------------------------
extern "C" void kernel_launch(void* const* d_in, const int* in_sizes, int n_in,
                              void* d_out, int out_size) {
    const float* x   = (const float*)d_in[0];
    const float* w0  = (const float*)d_in[1];
    const float* b0  = (const float*)d_in[2];
    const float* s0  = (const float*)d_in[3];
    const float* w1  = (const float*)d_in[4];
    const float* b1  = (const float*)d_in[5];
    const float* s1  = (const float*)d_in[6];
    const float* w2  = (const float*)d_in[7];
    const float* b2  = (const float*)d_in[8];
    const float* s2  = (const float*)d_in[9];
    const float* w3  = (const float*)d_in[10];
    const float* b3  = (const float*)d_in[11];
    const float* s3  = (const float*)d_in[12];
    const float* wm0 = (const float*)d_in[13];
    const float* bm0 = (const float*)d_in[14];
    const float* wm1 = (const float*)d_in[15];
    const float* bm1 = (const float*)d_in[16];

    int B = in_sizes[0] / 4096;
    if (B > MAXB) B = MAXB;

    cudaFuncSetAttribute((const void*)gauss_mma_kernel,
                         cudaFuncAttributeMaxDynamicSharedMemorySize, GM_SMEM);
    cudaFuncSetAttribute((const void*)compress_mma_kernel,
                         cudaFuncAttributeMaxDynamicSharedMemorySize, C2_SMEM);

    kprep_kernel<<<1, 256>>>(s0, s1, s2, s3);
    wprep_kernel<<<160, 512>>>(wm0);
    gauss_mma_kernel<<<(B + 7) / 8, 512, GM_SMEM>>>(
        x, w0, b0, w1, b1, w2, b2, w3, b3, B);
    compress_mma_kernel<<<(B + 63) / 64, 320, C2_SMEM>>>(
        bm0, wm1, bm1, (float*)d_out, B);
}

// round 16
// speedup vs baseline: 1.5416x; 1.1943x over previous
#include <cuda_runtime.h>
#include <cuda_bf16.h>
#include <cstdint>

// ---------------------------------------------------------------------------
// GaussianNNHeightmapEncoder — R15
//   gauss: 4 samples/CTA, 256 thr, 2 CTAs/SM. K delivered as register
//   fragments via LDG from a precomputed fragment-order gmem array (no KA
//   smem, no staging phases). W1-3 staged via cp.async from presplit image.
//   compress: R13/R14 version (measured 134.6 us) — unchanged.
// ---------------------------------------------------------------------------

#define MAXB 16384

__device__ float g_K[4 * 64 * 64];
__device__ uint4 g_Kfhi[4 * 4 * 4 * 32];           // [l][mt][ks][lane] A-fragments
__device__ uint4 g_Kflo[4 * 4 * 4 * 32];
__device__ __nv_bfloat16 g_Wimg_hi[112 * 40];      // W1/W2/W3 padded smem image
__device__ __nv_bfloat16 g_Wimg_lo[112 * 40];
__device__ __nv_bfloat16 g_hi[(size_t)MAXB * 4096];
__device__ __nv_bfloat16 g_lo[(size_t)MAXB * 4096];
__device__ __nv_bfloat16 g_w0hi[80 * 4096];
__device__ __nv_bfloat16 g_w0lo[80 * 4096];

__device__ __forceinline__ float lrelu(float v) { return fmaxf(v, 0.01f * v); }

__device__ __forceinline__ uint32_t smem_u32(const void* p) {
    uint32_t a;
    asm("{ .reg .u64 t; cvta.to.shared.u64 t, %1; cvt.u32.u64 %0, t; }" : "=r"(a) : "l"(p));
    return a;
}

__device__ __forceinline__ void split_bf16(float v, __nv_bfloat16& h, __nv_bfloat16& l) {
    h = __float2bfloat16(v);
    l = __float2bfloat16(v - __bfloat162float(h));
}
__device__ __forceinline__ void split2(float v0, float v1, uint32_t& hi, uint32_t& lo) {
    __nv_bfloat16 h0, l0, h1, l1;
    split_bf16(v0, h0, l0);
    split_bf16(v1, h1, l1);
    __nv_bfloat162 H, L;
    H.x = h0; H.y = h1;
    L.x = l0; L.y = l1;
    hi = *(uint32_t*)&H;
    lo = *(uint32_t*)&L;
}

// ---- async copy / ldmatrix / mma helpers ----
__device__ __forceinline__ void cp16(uint32_t dst, const void* src, int sz) {
    asm volatile("cp.async.cg.shared.global [%0], [%1], 16, %2;"
                 :: "r"(dst), "l"(src), "r"(sz) : "memory");
}
__device__ __forceinline__ void cp_commit() {
    asm volatile("cp.async.commit_group;" ::: "memory");
}
template <int N>
__device__ __forceinline__ void cp_wait() {
    asm volatile("cp.async.wait_group %0;" :: "n"(N) : "memory");
}
__device__ __forceinline__ void ldsm4(uint32_t* r, uint32_t addr) {
    asm volatile("ldmatrix.sync.aligned.m8n8.x4.shared.b16 {%0,%1,%2,%3}, [%4];"
                 : "=r"(r[0]), "=r"(r[1]), "=r"(r[2]), "=r"(r[3]) : "r"(addr));
}
__device__ __forceinline__ void mma16816(float* d, const uint32_t* a, const uint32_t* b) {
    asm volatile(
        "mma.sync.aligned.m16n8k16.row.col.f32.bf16.bf16.f32 "
        "{%0,%1,%2,%3}, {%4,%5,%6,%7}, {%8,%9}, {%0,%1,%2,%3};"
        : "+f"(d[0]), "+f"(d[1]), "+f"(d[2]), "+f"(d[3])
        : "r"(a[0]), "r"(a[1]), "r"(a[2]), "r"(a[3]), "r"(b[0]), "r"(b[1]));
}

// ---------------------------------------------------------------------------
// Kernel P: normalized Gaussian kernels (fp32)
// ---------------------------------------------------------------------------
__global__ void kprep_kernel(const float* __restrict__ s0, const float* __restrict__ s1,
                             const float* __restrict__ s2, const float* __restrict__ s3) {
    int tid = threadIdx.x;
    if (tid >= 256) return;
    int l = tid >> 6, i = tid & 63;
    float sig = (l == 0) ? s0[0] : (l == 1) ? s1[0] : (l == 2) ? s2[0] : s3[0];
    float inv = 1.0f / (2.0f * sig * sig);
    float e[64];
    float sum = 0.0f;
#pragma unroll 8
    for (int j = 0; j < 64; j++) {
        float d = (float)(i - j);
        e[j] = __expf(-d * d * inv);
        sum += e[j];
    }
    float r = 1.0f / fmaxf(sum, 1e-12f);
    float* dst = g_K + (l * 64 + i) * 64;
#pragma unroll 8
    for (int j = 0; j < 64; j++) dst[j] = e[j] * r;
}

// ---------------------------------------------------------------------------
// Kernel F: K -> mma A-fragment order (hi/lo split), [l][mt][ks][lane]
// ---------------------------------------------------------------------------
__global__ void kfrag_kernel() {
    int t = blockIdx.x * 512 + threadIdx.x;        // 2048 threads total
    if (t >= 2048) return;
    int lane = t & 31, ks = (t >> 5) & 3, mt = (t >> 7) & 3, l = t >> 9;
    const float* K = g_K + l * 4096;
    int r = mt * 16 + (lane >> 2);
    int c = ks * 16 + (lane & 3) * 2;
    uint32_t hi[4], lo[4];
    split2(K[r * 64 + c],           K[r * 64 + c + 1],           hi[0], lo[0]);  // a0
    split2(K[(r + 8) * 64 + c],     K[(r + 8) * 64 + c + 1],     hi[1], lo[1]);  // a1
    split2(K[r * 64 + c + 8],       K[r * 64 + c + 9],           hi[2], lo[2]);  // a2
    split2(K[(r + 8) * 64 + c + 8], K[(r + 8) * 64 + c + 9],     hi[3], lo[3]);  // a3
    int idx = ((l * 4 + mt) * 4 + ks) * 32 + lane;
    g_Kfhi[idx] = make_uint4(hi[0], hi[1], hi[2], hi[3]);
    g_Kflo[idx] = make_uint4(lo[0], lo[1], lo[2], lo[3]);
}

// ---------------------------------------------------------------------------
// Kernel W: split wm0 into bf16 hi/lo
// ---------------------------------------------------------------------------
__global__ void wprep_kernel(const float* __restrict__ wm0) {
    int idx = blockIdx.x * 512 + threadIdx.x;
    if (idx >= 81920) return;
    float4 v = *(const float4*)(wm0 + (size_t)idx * 4);
    __nv_bfloat16 h[4], l[4];
    split_bf16(v.x, h[0], l[0]);
    split_bf16(v.y, h[1], l[1]);
    split_bf16(v.z, h[2], l[2]);
    split_bf16(v.w, h[3], l[3]);
    *(uint2*)(g_w0hi + (size_t)idx * 4) = *(uint2*)h;
    *(uint2*)(g_w0lo + (size_t)idx * 4) = *(uint2*)l;
}

// ---------------------------------------------------------------------------
// Kernel WI: build W1/W2/W3 padded smem image (112 rows x 40 cols, zeros incl.)
// ---------------------------------------------------------------------------
__global__ void wimg_kernel(const float* __restrict__ w1, const float* __restrict__ w2,
                            const float* __restrict__ w3) {
    int t = blockIdx.x * 512 + threadIdx.x;
    if (t >= 4480) return;
    int row = t / 40, c = t % 40;
    float v = 0.0f;
    if (row < 16)      { if (c < 8)  v = w1[row * 8 + c]; }
    else if (row < 48) { if (c < 16) v = w2[(row - 16) * 16 + c]; }
    else               { if (c < 32) v = w3[(row - 48) * 32 + c]; }
    __nv_bfloat16 h, l;
    split_bf16(v, h, l);
    g_Wimg_hi[t] = h;
    g_Wimg_lo[t] = l;
}

// ---------------------------------------------------------------------------
// gauss smem layout (bytes) — 4 samples / CTA, 256 threads
//   W:   [112][40] bf16 image (80 B rows)
//   RM:  state row-major [256][40] bf16
//   CM:  state chan-major [128][72] bf16 (144 B rows)
// ---------------------------------------------------------------------------
#define GS_B0    0
#define GS_B1    32
#define GS_B2    96
#define GS_B3    224
#define GS_W0F   512
#define GS_W_HI  2560
#define GS_W_LO  11520
#define GS_RM_HI 20480
#define GS_RM_LO 40960
#define GS_CM_HI 61440
#define GS_CM_LO 79872
#define GS_SMEM  98304

// K-mul: D[64 x 4C] = K @ CM^T ; K fragments via LDG. -> CM (lrelu) or RM.
template <int C, bool TO_CM>
__device__ __forceinline__ void kmul_mma(char* smem, uint32_t sb, int lane, int w, int l) {
    constexpr int CH = C / 4;
    constexpr int SH = (C == 8) ? 3 : (C == 16) ? 4 : 5;
    int mt = w & 3;
    int n0t = (w >> 2) * CH;
    int g = lane >> 3;
    float acc[CH][4];
#pragma unroll
    for (int t = 0; t < CH; t++)
#pragma unroll
        for (int e = 0; e < 4; e++) acc[t][e] = 0.0f;

    const uint4* kfh = g_Kfhi + ((l * 4 + mt) * 4) * 32 + lane;
    const uint4* kfl = g_Kflo + ((l * 4 + mt) * 4) * 32 + lane;
#pragma unroll
    for (int ks = 0; ks < 4; ks++) {
        uint4 fh = kfh[ks * 32];
        uint4 fl = kfl[ks * 32];
        uint32_t ahi[4] = {fh.x, fh.y, fh.z, fh.w};
        uint32_t alo[4] = {fl.x, fl.y, fl.z, fl.w};
#pragma unroll
        for (int p = 0; p < CH / 2; p++) {
            uint32_t brow = (uint32_t)((n0t + p * 2) * 8 + (g >> 1) * 8 + (lane & 7)) * 144
                          + (uint32_t)(g & 1) * 16 + ks * 32;
            uint32_t bhi[4], blo[4];
            ldsm4(bhi, sb + GS_CM_HI + brow);
            ldsm4(blo, sb + GS_CM_LO + brow);
            mma16816(acc[p * 2],     ahi, bhi);
            mma16816(acc[p * 2 + 1], ahi, bhi + 2);
            mma16816(acc[p * 2],     alo, bhi);
            mma16816(acc[p * 2 + 1], alo, bhi + 2);
            mma16816(acc[p * 2],     ahi, blo);
            mma16816(acc[p * 2 + 1], ahi, blo + 2);
        }
    }
    if (TO_CM) __syncthreads();
    int r0 = mt * 16 + (lane >> 2);
    int cp = (lane & 3) * 2;
#pragma unroll
    for (int t = 0; t < CH; t++) {
        int nn = (n0t + t) * 8 + cp;
#pragma unroll
        for (int h2 = 0; h2 < 2; h2++) {
            int i = r0 + h2 * 8;
            float v0 = acc[t][h2 * 2 + 0], v1 = acc[t][h2 * 2 + 1];
            if (TO_CM) {
                v0 = lrelu(v0); v1 = lrelu(v1);
                __nv_bfloat16 h0, l0, h1, l1;
                split_bf16(v0, h0, l0);
                split_bf16(v1, h1, l1);
                *(__nv_bfloat16*)(smem + GS_CM_HI + (((nn    ) * 72 + i) << 1)) = h0;
                *(__nv_bfloat16*)(smem + GS_CM_HI + (((nn + 1) * 72 + i) << 1)) = h1;
                *(__nv_bfloat16*)(smem + GS_CM_LO + (((nn    ) * 72 + i) << 1)) = l0;
                *(__nv_bfloat16*)(smem + GS_CM_LO + (((nn + 1) * 72 + i) << 1)) = l1;
            } else {
                int s = nn >> SH, c = nn & (C - 1);
                uint32_t off = (((uint32_t)(s * 64 + i) * 40 + c) << 1);
                uint32_t hi, lo;
                split2(v0, v1, hi, lo);
                *(uint32_t*)(smem + GS_RM_HI + off) = hi;
                *(uint32_t*)(smem + GS_RM_LO + off) = lo;
            }
        }
    }
}

// W-mul: D[256 x Cout] = RM @ W^T (+bias, lrelu); -> CM (L1,2) or gmem (L3)
template <int CIN, int COUT, int L>
__device__ __forceinline__ void wmul_mma(char* smem, uint32_t sb, int lane, int w,
                                         const float* __restrict__ bias,
                                         long bbase, int Bn) {
    constexpr int KS = (CIN + 15) / 16;
    constexpr int NT = COUT / 8;
    constexpr int NC = (NT < 4) ? NT : 4;
    constexpr int NCH = NT / NC;
    constexpr int WROW = (L == 1) ? 0 : (L == 2) ? 16 : 48;
    int mt0 = w * 2;
    int g = lane >> 3;
    int r0 = (lane >> 2);
    int cp = (lane & 3) * 2;
#pragma unroll
    for (int ch = 0; ch < NCH; ch++) {
        float acc[2][NC][4];
#pragma unroll
        for (int m = 0; m < 2; m++)
#pragma unroll
            for (int t = 0; t < NC; t++)
#pragma unroll
                for (int e = 0; e < 4; e++) acc[m][t][e] = 0.0f;
#pragma unroll
        for (int ks = 0; ks < KS; ks++) {
            uint32_t ahi[2][4], alo[2][4];
#pragma unroll
            for (int m = 0; m < 2; m++) {
                uint32_t ao = (uint32_t)((mt0 + m) * 16 + (lane & 15)) * 80
                            + (uint32_t)(lane >> 4) * 16 + ks * 32;
                ldsm4(ahi[m], sb + GS_RM_HI + ao);
                ldsm4(alo[m], sb + GS_RM_LO + ao);
            }
#pragma unroll
            for (int p = 0; p < NC / 2; p++) {
                uint32_t brow = (uint32_t)(WROW + (ch * NC + p * 2) * 8 + (g >> 1) * 8 + (lane & 7)) * 80
                              + (uint32_t)(g & 1) * 16 + ks * 32;
                uint32_t bhi[4], blo[4];
                ldsm4(bhi, sb + GS_W_HI + brow);
                ldsm4(blo, sb + GS_W_LO + brow);
#pragma unroll
                for (int m = 0; m < 2; m++) {
                    mma16816(acc[m][p * 2],     ahi[m], bhi);
                    mma16816(acc[m][p * 2 + 1], ahi[m], bhi + 2);
                    mma16816(acc[m][p * 2],     alo[m], bhi);
                    mma16816(acc[m][p * 2 + 1], alo[m], bhi + 2);
                    mma16816(acc[m][p * 2],     ahi[m], blo);
                    mma16816(acc[m][p * 2 + 1], ahi[m], blo + 2);
                }
            }
        }
#pragma unroll
        for (int m = 0; m < 2; m++) {
#pragma unroll
            for (int t = 0; t < NC; t++) {
                int o = (ch * NC + t) * 8 + cp;
                float b0v = bias[o], b1v = bias[o + 1];
#pragma unroll
                for (int h2 = 0; h2 < 2; h2++) {
                    int mg = (mt0 + m) * 16 + r0 + h2 * 8;
                    int s = mg >> 6, i = mg & 63;
                    float v0 = lrelu(acc[m][t][h2 * 2 + 0] + b0v);
                    float v1 = lrelu(acc[m][t][h2 * 2 + 1] + b1v);
                    if (L < 3) {
                        int row = s * COUT + o;
                        __nv_bfloat16 h0, l0, h1, l1;
                        split_bf16(v0, h0, l0);
                        split_bf16(v1, h1, l1);
                        *(__nv_bfloat16*)(smem + GS_CM_HI + (((row    ) * 72 + i) << 1)) = h0;
                        *(__nv_bfloat16*)(smem + GS_CM_HI + (((row + 1) * 72 + i) << 1)) = h1;
                        *(__nv_bfloat16*)(smem + GS_CM_LO + (((row    ) * 72 + i) << 1)) = l0;
                        *(__nv_bfloat16*)(smem + GS_CM_LO + (((row + 1) * 72 + i) << 1)) = l1;
                    } else {
                        long bb = bbase + s;
                        if (bb < Bn) {
                            uint32_t hi, lo;
                            split2(v0, v1, hi, lo);
                            size_t word = ((size_t)bb * 4096 + (size_t)i * 64 + o) >> 1;
                            ((uint32_t*)g_hi)[word] = hi;
                            ((uint32_t*)g_lo)[word] = lo;
                        }
                    }
                }
            }
        }
    }
}

__global__ __launch_bounds__(256, 2) void gauss_mma_kernel(
    const float* __restrict__ x,
    const float* __restrict__ w0, const float* __restrict__ b0,
    const float* __restrict__ b1, const float* __restrict__ b2,
    const float* __restrict__ b3, int B) {
    extern __shared__ char smem[];
    uint32_t sb = smem_u32(smem);
    int tid = threadIdx.x, lane = tid & 31, w = tid >> 5;

    // async-stage W image (560 x 16B per half)
    for (int t = tid; t < 560; t += 256) {
        cp16(sb + GS_W_HI + t * 16, ((const char*)g_Wimg_hi) + t * 16, 16);
        cp16(sb + GS_W_LO + t * 16, ((const char*)g_Wimg_lo) + t * 16, 16);
    }
    cp_commit();

    // zero RM pad cols 8..15 (needed for L1's k16 ldmatrix)
    for (int t = tid; t < 2048; t += 256) {
        int half = t >> 10, row = (t >> 2) & 255, q = t & 3;
        *(uint32_t*)(smem + GS_RM_HI + half * 20480 + row * 80 + 16 + q * 4) = 0u;
    }

    // stage consts
    float* W0s = (float*)(smem + GS_W0F);
    for (int t = tid; t < 512; t += 256) W0s[t] = w0[t];
    if (tid < 8)  ((float*)(smem + GS_B0))[tid] = b0[tid];
    if (tid < 16) ((float*)(smem + GS_B1))[tid] = b1[tid];
    if (tid < 32) ((float*)(smem + GS_B2))[tid] = b2[tid];
    if (tid < 64) ((float*)(smem + GS_B3))[tid] = b3[tid];
    __syncthreads();

    // ---- L0 (FFMA): XP = X @ W0^T + b0 -> CM[(s*8+o)][i]
    {
        int s = tid >> 6, i = tid & 63;
        long b = (long)blockIdx.x * 4 + s;
        bool act = (b < B);
        const float* xrow = x + (act ? b * 4096 + (long)i * 64 : 0);
        const float* b0s = (const float*)(smem + GS_B0);
        float acc[8];
#pragma unroll
        for (int o = 0; o < 8; o++) acc[o] = b0s[o];
#pragma unroll
        for (int half = 0; half < 2; half++) {
            float4 xr[8];
#pragma unroll
            for (int q = 0; q < 8; q++)
                xr[q] = act ? *(const float4*)&xrow[half * 32 + q * 4]
                            : make_float4(0.f, 0.f, 0.f, 0.f);
#pragma unroll
            for (int o = 0; o < 8; o++) {
#pragma unroll
                for (int q = 0; q < 8; q++) {
                    float4 wv = *(const float4*)&W0s[o * 64 + half * 32 + q * 4];
                    acc[o] = fmaf(xr[q].x, wv.x, fmaf(xr[q].y, wv.y,
                             fmaf(xr[q].z, wv.z, fmaf(xr[q].w, wv.w, acc[o]))));
                }
            }
        }
#pragma unroll
        for (int o = 0; o < 8; o++) {
            __nv_bfloat16 h, l;
            split_bf16(acc[o], h, l);
            *(__nv_bfloat16*)(smem + GS_CM_HI + (((s * 8 + o) * 72 + i) << 1)) = h;
            *(__nv_bfloat16*)(smem + GS_CM_LO + (((s * 8 + o) * 72 + i) << 1)) = l;
        }
    }
    cp_wait<0>();                                   // W image arrived
    __syncthreads();

    const float* b1s = (const float*)(smem + GS_B1);
    const float* b2s = (const float*)(smem + GS_B2);
    const float* b3s = (const float*)(smem + GS_B3);
    long bbase = (long)blockIdx.x * 4;

    kmul_mma<8, true>(smem, sb, lane, w, 0);        // K0 @ XP, lrelu -> CM in-place
    __syncthreads();

    kmul_mma<8, false>(smem, sb, lane, w, 1);       // K1 @ h -> RM
    __syncthreads();
    wmul_mma<8, 16, 1>(smem, sb, lane, w, b1s, bbase, B);   // -> CM
    __syncthreads();

    kmul_mma<16, false>(smem, sb, lane, w, 2);      // K2 @ h -> RM
    __syncthreads();
    wmul_mma<16, 32, 2>(smem, sb, lane, w, b2s, bbase, B);  // -> CM
    __syncthreads();

    kmul_mma<32, false>(smem, sb, lane, w, 3);      // K3 @ h -> RM
    __syncthreads();
    wmul_mma<32, 64, 3>(smem, sb, lane, w, b3s, bbase, B);  // -> g_hi/g_lo
}

// ---------------------------------------------------------------------------
// Kernel C (HMMA): M=64 tile, 320 threads, 2 CTAs/SM — unchanged (134.6 us)
// ---------------------------------------------------------------------------
#define C2_SW1    0
#define C2_STG0   19456
#define C2_A_HI   0
#define C2_A_LO   9216
#define C2_B_HI   18432
#define C2_B_LO   29952
#define C2_STG_SZ 41472
#define C2_SMEM   (C2_STG0 + 2 * C2_STG_SZ)        // 102400

__global__ __launch_bounds__(320, 2) void compress_mma_kernel(
    const float* __restrict__ bm0, const float* __restrict__ wm1,
    const float* __restrict__ bm1, float* __restrict__ out, int B) {
    extern __shared__ char smem[];
    uint32_t sb = smem_u32(smem);
    int tid = threadIdx.x;
    long m0 = (long)blockIdx.x * 64;

    float* sW1 = (float*)(smem + C2_SW1);
    for (int t = tid; t < 4800; t += 320) sW1[t] = wm1[t];

    int lane = tid & 31, w = tid >> 5;
    int nw = (w < 5) ? w : w - 5;
    int mw = (w < 5) ? 0 : 1;
    int g = lane >> 3;

    auto load_chunk = [&](int c, int bsel) {
        uint32_t stg = sb + C2_STG0 + bsel * C2_STG_SZ;
        int k0 = c * 64;
        for (int q = tid; q < 512; q += 320) {
            int m = q >> 3, kk = q & 7;
            long gm = m0 + m;
            int ok = (gm < B);
            size_t off = (size_t)(ok ? gm : 0) * 4096 + k0 + kk * 8;
            int sz = ok ? 16 : 0;
            uint32_t d = stg + m * 144 + kk * 16;
            cp16(d + C2_A_HI, g_hi + off, sz);
            cp16(d + C2_A_LO, g_lo + off, sz);
        }
        for (int q = tid; q < 640; q += 320) {
            int o = q >> 3, kk = q & 7;
            size_t off = (size_t)o * 4096 + k0 + kk * 8;
            uint32_t d = stg + o * 144 + kk * 16;
            cp16(d + C2_B_HI, g_w0hi + off, 16);
            cp16(d + C2_B_LO, g_w0lo + off, 16);
        }
        cp_commit();
    };

    float acc[2][2][4];
#pragma unroll
    for (int mt = 0; mt < 2; mt++)
#pragma unroll
        for (int nt = 0; nt < 2; nt++)
#pragma unroll
            for (int e = 0; e < 4; e++) acc[mt][nt][e] = 0.0f;

    load_chunk(0, 0);
    load_chunk(1, 1);

    uint32_t aoff0 = (uint32_t)(mw * 32 + (lane & 15)) * 144 + (uint32_t)(lane >> 4) * 16;
    uint32_t boff0 = (uint32_t)(nw * 16 + (g >> 1) * 8 + (lane & 7)) * 144 + (uint32_t)(g & 1) * 16;

#pragma unroll 1
    for (int c = 0; c < 64; c++) {
        int bsel = c & 1;
        cp_wait<1>();
        __syncthreads();
        uint32_t stg = sb + C2_STG0 + bsel * C2_STG_SZ;

#pragma unroll
        for (int ks = 0; ks < 4; ks++) {
            uint32_t ahi[2][4], alo[2][4], bhi[4], blo[4];
            uint32_t ao = stg + aoff0 + ks * 32;
            ldsm4(ahi[0], ao + C2_A_HI);
            ldsm4(ahi[1], ao + C2_A_HI + 16 * 144);
            ldsm4(alo[0], ao + C2_A_LO);
            ldsm4(alo[1], ao + C2_A_LO + 16 * 144);
            uint32_t bo = stg + boff0 + ks * 32;
            ldsm4(bhi, bo + C2_B_HI);
            ldsm4(blo, bo + C2_B_LO);
#pragma unroll
            for (int mt = 0; mt < 2; mt++)
#pragma unroll
                for (int nt = 0; nt < 2; nt++) {
                    mma16816(acc[mt][nt], ahi[mt], bhi + nt * 2);
                    mma16816(acc[mt][nt], alo[mt], bhi + nt * 2);
                    mma16816(acc[mt][nt], ahi[mt], blo + nt * 2);
                }
        }
        __syncthreads();
        if (c + 2 < 64) load_chunk(c + 2, bsel);
        else cp_commit();
    }

    float* h1 = (float*)(smem + C2_STG0);
    int qrow = lane >> 2;
    int qcol = (lane & 3) * 2;
#pragma unroll
    for (int mt = 0; mt < 2; mt++)
#pragma unroll
        for (int i = 0; i < 2; i++) {
            int r = mw * 32 + mt * 16 + qrow + i * 8;
#pragma unroll
            for (int nt = 0; nt < 2; nt++)
#pragma unroll
                for (int j = 0; j < 2; j++) {
                    int col = nw * 16 + nt * 8 + qcol + j;
                    h1[r * 81 + col] = lrelu(acc[mt][nt][i * 2 + j] + __ldg(&bm0[col]));
                }
        }
    __syncthreads();

#pragma unroll 1
    for (int ii = 0; ii < 12; ii++) {
        int idx = tid + ii * 320;
        int m = idx & 63, o2 = idx >> 6;
        float a = __ldg(&bm1[o2]);
#pragma unroll 4
        for (int c4 = 0; c4 < 80; c4 += 4) {
            float4 wv = *(const float4*)&sW1[o2 * 80 + c4];
            a = fmaf(h1[m * 81 + c4 + 0], wv.x,
                fmaf(h1[m * 81 + c4 + 1], wv.y,
                fmaf(h1[m * 81 + c4 + 2], wv.z,
                fmaf(h1[m * 81 + c4 + 3], wv.w, a))));
        }
        long gm = m0 + m;
        if (gm < B) out[gm * 60 + o2] = lrelu(a);
    }
}

// ---------------------------------------------------------------------------
extern "C" void kernel_launch(void* const* d_in, const int* in_sizes, int n_in,
                              void* d_out, int out_size) {
    const float* x   = (const float*)d_in[0];
    const float* w0  = (const float*)d_in[1];
    const float* b0  = (const float*)d_in[2];
    const float* s0  = (const float*)d_in[3];
    const float* w1  = (const float*)d_in[4];
    const float* b1  = (const float*)d_in[5];
    const float* s1  = (const float*)d_in[6];
    const float* w2  = (const float*)d_in[7];
    const float* b2  = (const float*)d_in[8];
    const float* s2  = (const float*)d_in[9];
    const float* w3  = (const float*)d_in[10];
    const float* b3  = (const float*)d_in[11];
    const float* s3  = (const float*)d_in[12];
    const float* wm0 = (const float*)d_in[13];
    const float* bm0 = (const float*)d_in[14];
    const float* wm1 = (const float*)d_in[15];
    const float* bm1 = (const float*)d_in[16];

    int B = in_sizes[0] / 4096;
    if (B > MAXB) B = MAXB;

    cudaFuncSetAttribute((const void*)gauss_mma_kernel,
                         cudaFuncAttributeMaxDynamicSharedMemorySize, GS_SMEM);
    cudaFuncSetAttribute((const void*)compress_mma_kernel,
                         cudaFuncAttributeMaxDynamicSharedMemorySize, C2_SMEM);

    kprep_kernel<<<1, 256>>>(s0, s1, s2, s3);
    kfrag_kernel<<<4, 512>>>();
    wprep_kernel<<<160, 512>>>(wm0);
    wimg_kernel<<<9, 512>>>(w1, w2, w3);
    gauss_mma_kernel<<<(B + 3) / 4, 256, GS_SMEM>>>(x, w0, b0, b1, b2, b3, B);
    compress_mma_kernel<<<(B + 63) / 64, 320, C2_SMEM>>>(
        bm0, wm1, bm1, (float*)d_out, B);
}

// round 17
// speedup vs baseline: 1.5685x; 1.0175x over previous
#include <cuda_runtime.h>
#include <cuda_bf16.h>
#include <cstdint>

// ---------------------------------------------------------------------------
// GaussianNNHeightmapEncoder — R17
//   compress: warp tile widened to 32x40 (R8 addressing), 128 thr / 4 warps,
//             M=64 tiles, 2 CTAs/SM, one wave — targets the L1(ldsm) cap.
//   gauss: unchanged from R15 (4 samples/CTA, reg-fragment K, ~295 us).
//   prep: 4 kernels -> 2 (K fragments built from smem; wimg folded in wprep).
// ---------------------------------------------------------------------------

#define MAXB 16384

__device__ uint4 g_Kfhi[4 * 4 * 4 * 32];           // [l][mt][ks][lane] A-fragments
__device__ uint4 g_Kflo[4 * 4 * 4 * 32];
__device__ __nv_bfloat16 g_Wimg_hi[112 * 40];      // W1/W2/W3 padded smem image
__device__ __nv_bfloat16 g_Wimg_lo[112 * 40];
__device__ __nv_bfloat16 g_hi[(size_t)MAXB * 4096];
__device__ __nv_bfloat16 g_lo[(size_t)MAXB * 4096];
__device__ __nv_bfloat16 g_w0hi[80 * 4096];
__device__ __nv_bfloat16 g_w0lo[80 * 4096];

__device__ __forceinline__ float lrelu(float v) { return fmaxf(v, 0.01f * v); }

__device__ __forceinline__ uint32_t smem_u32(const void* p) {
    uint32_t a;
    asm("{ .reg .u64 t; cvta.to.shared.u64 t, %1; cvt.u32.u64 %0, t; }" : "=r"(a) : "l"(p));
    return a;
}

__device__ __forceinline__ void split_bf16(float v, __nv_bfloat16& h, __nv_bfloat16& l) {
    h = __float2bfloat16(v);
    l = __float2bfloat16(v - __bfloat162float(h));
}
__device__ __forceinline__ void split2(float v0, float v1, uint32_t& hi, uint32_t& lo) {
    __nv_bfloat16 h0, l0, h1, l1;
    split_bf16(v0, h0, l0);
    split_bf16(v1, h1, l1);
    __nv_bfloat162 H, L;
    H.x = h0; H.y = h1;
    L.x = l0; L.y = l1;
    hi = *(uint32_t*)&H;
    lo = *(uint32_t*)&L;
}

// ---- async copy / ldmatrix / mma helpers ----
__device__ __forceinline__ void cp16(uint32_t dst, const void* src, int sz) {
    asm volatile("cp.async.cg.shared.global [%0], [%1], 16, %2;"
                 :: "r"(dst), "l"(src), "r"(sz) : "memory");
}
__device__ __forceinline__ void cp_commit() {
    asm volatile("cp.async.commit_group;" ::: "memory");
}
template <int N>
__device__ __forceinline__ void cp_wait() {
    asm volatile("cp.async.wait_group %0;" :: "n"(N) : "memory");
}
__device__ __forceinline__ void ldsm4(uint32_t* r, uint32_t addr) {
    asm volatile("ldmatrix.sync.aligned.m8n8.x4.shared.b16 {%0,%1,%2,%3}, [%4];"
                 : "=r"(r[0]), "=r"(r[1]), "=r"(r[2]), "=r"(r[3]) : "r"(addr));
}
__device__ __forceinline__ void ldsm2(uint32_t* r, uint32_t addr) {
    asm volatile("ldmatrix.sync.aligned.m8n8.x2.shared.b16 {%0,%1}, [%2];"
                 : "=r"(r[0]), "=r"(r[1]) : "r"(addr));
}
__device__ __forceinline__ void mma16816(float* d, const uint32_t* a, const uint32_t* b) {
    asm volatile(
        "mma.sync.aligned.m16n8k16.row.col.f32.bf16.bf16.f32 "
        "{%0,%1,%2,%3}, {%4,%5,%6,%7}, {%8,%9}, {%0,%1,%2,%3};"
        : "+f"(d[0]), "+f"(d[1]), "+f"(d[2]), "+f"(d[3])
        : "r"(a[0]), "r"(a[1]), "r"(a[2]), "r"(a[3]), "r"(b[0]), "r"(b[1]));
}

// ---------------------------------------------------------------------------
// Kernel P: K matrices in smem, emit mma A-fragments (hi/lo) directly.
// ---------------------------------------------------------------------------
__global__ void kprep2_kernel(const float* __restrict__ s0, const float* __restrict__ s1,
                              const float* __restrict__ s2, const float* __restrict__ s3) {
    extern __shared__ float Ksm[];                 // 4*64*64 fp32 = 64 KB
    int tid = threadIdx.x;
    {
        int l = tid >> 6, i = tid & 63;
        float sig = (l == 0) ? s0[0] : (l == 1) ? s1[0] : (l == 2) ? s2[0] : s3[0];
        float inv = 1.0f / (2.0f * sig * sig);
        float e[64];
        float sum = 0.0f;
#pragma unroll 8
        for (int j = 0; j < 64; j++) {
            float d = (float)(i - j);
            e[j] = __expf(-d * d * inv);
            sum += e[j];
        }
        float r = 1.0f / fmaxf(sum, 1e-12f);
        float* dst = Ksm + (l * 64 + i) * 64;
#pragma unroll 8
        for (int j = 0; j < 64; j++) dst[j] = e[j] * r;
    }
    __syncthreads();
    for (int t = tid; t < 2048; t += 256) {
        int lane = t & 31, ks = (t >> 5) & 3, mt = (t >> 7) & 3, l = t >> 9;
        const float* K = Ksm + l * 4096;
        int r = mt * 16 + (lane >> 2);
        int c = ks * 16 + (lane & 3) * 2;
        uint32_t hi[4], lo[4];
        split2(K[r * 64 + c],           K[r * 64 + c + 1],       hi[0], lo[0]);
        split2(K[(r + 8) * 64 + c],     K[(r + 8) * 64 + c + 1], hi[1], lo[1]);
        split2(K[r * 64 + c + 8],       K[r * 64 + c + 9],       hi[2], lo[2]);
        split2(K[(r + 8) * 64 + c + 8], K[(r + 8) * 64 + c + 9], hi[3], lo[3]);
        int idx = ((l * 4 + mt) * 4 + ks) * 32 + lane;
        g_Kfhi[idx] = make_uint4(hi[0], hi[1], hi[2], hi[3]);
        g_Kflo[idx] = make_uint4(lo[0], lo[1], lo[2], lo[3]);
    }
}

// ---------------------------------------------------------------------------
// Kernel W: split wm0 hi/lo + build W1/W2/W3 padded image (merged)
// ---------------------------------------------------------------------------
__global__ void wprep2_kernel(const float* __restrict__ wm0, const float* __restrict__ w1,
                              const float* __restrict__ w2, const float* __restrict__ w3) {
    int idx = blockIdx.x * 512 + threadIdx.x;
    if (idx < 81920) {
        float4 v = *(const float4*)(wm0 + (size_t)idx * 4);
        __nv_bfloat16 h[4], l[4];
        split_bf16(v.x, h[0], l[0]);
        split_bf16(v.y, h[1], l[1]);
        split_bf16(v.z, h[2], l[2]);
        split_bf16(v.w, h[3], l[3]);
        *(uint2*)(g_w0hi + (size_t)idx * 4) = *(uint2*)h;
        *(uint2*)(g_w0lo + (size_t)idx * 4) = *(uint2*)l;
    }
    if (idx < 4480) {
        int row = idx / 40, c = idx % 40;
        float v = 0.0f;
        if (row < 16)      { if (c < 8)  v = w1[row * 8 + c]; }
        else if (row < 48) { if (c < 16) v = w2[(row - 16) * 16 + c]; }
        else               { if (c < 32) v = w3[(row - 48) * 32 + c]; }
        __nv_bfloat16 h, l;
        split_bf16(v, h, l);
        g_Wimg_hi[idx] = h;
        g_Wimg_lo[idx] = l;
    }
}

// ---------------------------------------------------------------------------
// gauss smem layout (bytes) — 4 samples / CTA, 256 threads (unchanged R15)
// ---------------------------------------------------------------------------
#define GS_B0    0
#define GS_B1    32
#define GS_B2    96
#define GS_B3    224
#define GS_W0F   512
#define GS_W_HI  2560
#define GS_W_LO  11520
#define GS_RM_HI 20480
#define GS_RM_LO 40960
#define GS_CM_HI 61440
#define GS_CM_LO 79872
#define GS_SMEM  98304

// K-mul: D[64 x 4C] = K @ CM^T ; K fragments via LDG. -> CM (lrelu) or RM.
template <int C, bool TO_CM>
__device__ __forceinline__ void kmul_mma(char* smem, uint32_t sb, int lane, int w, int l) {
    constexpr int CH = C / 4;
    constexpr int SH = (C == 8) ? 3 : (C == 16) ? 4 : 5;
    int mt = w & 3;
    int n0t = (w >> 2) * CH;
    int g = lane >> 3;
    float acc[CH][4];
#pragma unroll
    for (int t = 0; t < CH; t++)
#pragma unroll
        for (int e = 0; e < 4; e++) acc[t][e] = 0.0f;

    const uint4* kfh = g_Kfhi + ((l * 4 + mt) * 4) * 32 + lane;
    const uint4* kfl = g_Kflo + ((l * 4 + mt) * 4) * 32 + lane;
#pragma unroll
    for (int ks = 0; ks < 4; ks++) {
        uint4 fh = kfh[ks * 32];
        uint4 fl = kfl[ks * 32];
        uint32_t ahi[4] = {fh.x, fh.y, fh.z, fh.w};
        uint32_t alo[4] = {fl.x, fl.y, fl.z, fl.w};
#pragma unroll
        for (int p = 0; p < CH / 2; p++) {
            uint32_t brow = (uint32_t)((n0t + p * 2) * 8 + (g >> 1) * 8 + (lane & 7)) * 144
                          + (uint32_t)(g & 1) * 16 + ks * 32;
            uint32_t bhi[4], blo[4];
            ldsm4(bhi, sb + GS_CM_HI + brow);
            ldsm4(blo, sb + GS_CM_LO + brow);
            mma16816(acc[p * 2],     ahi, bhi);
            mma16816(acc[p * 2 + 1], ahi, bhi + 2);
            mma16816(acc[p * 2],     alo, bhi);
            mma16816(acc[p * 2 + 1], alo, bhi + 2);
            mma16816(acc[p * 2],     ahi, blo);
            mma16816(acc[p * 2 + 1], ahi, blo + 2);
        }
    }
    if (TO_CM) __syncthreads();
    int r0 = mt * 16 + (lane >> 2);
    int cp = (lane & 3) * 2;
#pragma unroll
    for (int t = 0; t < CH; t++) {
        int nn = (n0t + t) * 8 + cp;
#pragma unroll
        for (int h2 = 0; h2 < 2; h2++) {
            int i = r0 + h2 * 8;
            float v0 = acc[t][h2 * 2 + 0], v1 = acc[t][h2 * 2 + 1];
            if (TO_CM) {
                v0 = lrelu(v0); v1 = lrelu(v1);
                __nv_bfloat16 h0, l0, h1, l1;
                split_bf16(v0, h0, l0);
                split_bf16(v1, h1, l1);
                *(__nv_bfloat16*)(smem + GS_CM_HI + (((nn    ) * 72 + i) << 1)) = h0;
                *(__nv_bfloat16*)(smem + GS_CM_HI + (((nn + 1) * 72 + i) << 1)) = h1;
                *(__nv_bfloat16*)(smem + GS_CM_LO + (((nn    ) * 72 + i) << 1)) = l0;
                *(__nv_bfloat16*)(smem + GS_CM_LO + (((nn + 1) * 72 + i) << 1)) = l1;
            } else {
                int s = nn >> SH, c = nn & (C - 1);
                uint32_t off = (((uint32_t)(s * 64 + i) * 40 + c) << 1);
                uint32_t hi, lo;
                split2(v0, v1, hi, lo);
                *(uint32_t*)(smem + GS_RM_HI + off) = hi;
                *(uint32_t*)(smem + GS_RM_LO + off) = lo;
            }
        }
    }
}

// W-mul: D[256 x Cout] = RM @ W^T (+bias, lrelu); -> CM (L1,2) or gmem (L3)
template <int CIN, int COUT, int L>
__device__ __forceinline__ void wmul_mma(char* smem, uint32_t sb, int lane, int w,
                                         const float* __restrict__ bias,
                                         long bbase, int Bn) {
    constexpr int KS = (CIN + 15) / 16;
    constexpr int NT = COUT / 8;
    constexpr int NC = (NT < 4) ? NT : 4;
    constexpr int NCH = NT / NC;
    constexpr int WROW = (L == 1) ? 0 : (L == 2) ? 16 : 48;
    int mt0 = w * 2;
    int g = lane >> 3;
    int r0 = (lane >> 2);
    int cp = (lane & 3) * 2;
#pragma unroll
    for (int ch = 0; ch < NCH; ch++) {
        float acc[2][NC][4];
#pragma unroll
        for (int m = 0; m < 2; m++)
#pragma unroll
            for (int t = 0; t < NC; t++)
#pragma unroll
                for (int e = 0; e < 4; e++) acc[m][t][e] = 0.0f;
#pragma unroll
        for (int ks = 0; ks < KS; ks++) {
            uint32_t ahi[2][4], alo[2][4];
#pragma unroll
            for (int m = 0; m < 2; m++) {
                uint32_t ao = (uint32_t)((mt0 + m) * 16 + (lane & 15)) * 80
                            + (uint32_t)(lane >> 4) * 16 + ks * 32;
                ldsm4(ahi[m], sb + GS_RM_HI + ao);
                ldsm4(alo[m], sb + GS_RM_LO + ao);
            }
#pragma unroll
            for (int p = 0; p < NC / 2; p++) {
                uint32_t brow = (uint32_t)(WROW + (ch * NC + p * 2) * 8 + (g >> 1) * 8 + (lane & 7)) * 80
                              + (uint32_t)(g & 1) * 16 + ks * 32;
                uint32_t bhi[4], blo[4];
                ldsm4(bhi, sb + GS_W_HI + brow);
                ldsm4(blo, sb + GS_W_LO + brow);
#pragma unroll
                for (int m = 0; m < 2; m++) {
                    mma16816(acc[m][p * 2],     ahi[m], bhi);
                    mma16816(acc[m][p * 2 + 1], ahi[m], bhi + 2);
                    mma16816(acc[m][p * 2],     alo[m], bhi);
                    mma16816(acc[m][p * 2 + 1], alo[m], bhi + 2);
                    mma16816(acc[m][p * 2],     ahi[m], blo);
                    mma16816(acc[m][p * 2 + 1], ahi[m], blo + 2);
                }
            }
        }
#pragma unroll
        for (int m = 0; m < 2; m++) {
#pragma unroll
            for (int t = 0; t < NC; t++) {
                int o = (ch * NC + t) * 8 + cp;
                float b0v = bias[o], b1v = bias[o + 1];
#pragma unroll
                for (int h2 = 0; h2 < 2; h2++) {
                    int mg = (mt0 + m) * 16 + r0 + h2 * 8;
                    int s = mg >> 6, i = mg & 63;
                    float v0 = lrelu(acc[m][t][h2 * 2 + 0] + b0v);
                    float v1 = lrelu(acc[m][t][h2 * 2 + 1] + b1v);
                    if (L < 3) {
                        int row = s * COUT + o;
                        __nv_bfloat16 h0, l0, h1, l1;
                        split_bf16(v0, h0, l0);
                        split_bf16(v1, h1, l1);
                        *(__nv_bfloat16*)(smem + GS_CM_HI + (((row    ) * 72 + i) << 1)) = h0;
                        *(__nv_bfloat16*)(smem + GS_CM_HI + (((row + 1) * 72 + i) << 1)) = h1;
                        *(__nv_bfloat16*)(smem + GS_CM_LO + (((row    ) * 72 + i) << 1)) = l0;
                        *(__nv_bfloat16*)(smem + GS_CM_LO + (((row + 1) * 72 + i) << 1)) = l1;
                    } else {
                        long bb = bbase + s;
                        if (bb < Bn) {
                            uint32_t hi, lo;
                            split2(v0, v1, hi, lo);
                            size_t word = ((size_t)bb * 4096 + (size_t)i * 64 + o) >> 1;
                            ((uint32_t*)g_hi)[word] = hi;
                            ((uint32_t*)g_lo)[word] = lo;
                        }
                    }
                }
            }
        }
    }
}

__global__ __launch_bounds__(256, 2) void gauss_mma_kernel(
    const float* __restrict__ x,
    const float* __restrict__ w0, const float* __restrict__ b0,
    const float* __restrict__ b1, const float* __restrict__ b2,
    const float* __restrict__ b3, int B) {
    extern __shared__ char smem[];
    uint32_t sb = smem_u32(smem);
    int tid = threadIdx.x, lane = tid & 31, w = tid >> 5;

    for (int t = tid; t < 560; t += 256) {
        cp16(sb + GS_W_HI + t * 16, ((const char*)g_Wimg_hi) + t * 16, 16);
        cp16(sb + GS_W_LO + t * 16, ((const char*)g_Wimg_lo) + t * 16, 16);
    }
    cp_commit();

    for (int t = tid; t < 2048; t += 256) {
        int half = t >> 10, row = (t >> 2) & 255, q = t & 3;
        *(uint32_t*)(smem + GS_RM_HI + half * 20480 + row * 80 + 16 + q * 4) = 0u;
    }

    float* W0s = (float*)(smem + GS_W0F);
    for (int t = tid; t < 512; t += 256) W0s[t] = w0[t];
    if (tid < 8)  ((float*)(smem + GS_B0))[tid] = b0[tid];
    if (tid < 16) ((float*)(smem + GS_B1))[tid] = b1[tid];
    if (tid < 32) ((float*)(smem + GS_B2))[tid] = b2[tid];
    if (tid < 64) ((float*)(smem + GS_B3))[tid] = b3[tid];
    __syncthreads();

    // ---- L0 (FFMA): XP = X @ W0^T + b0 -> CM[(s*8+o)][i]
    {
        int s = tid >> 6, i = tid & 63;
        long b = (long)blockIdx.x * 4 + s;
        bool act = (b < B);
        const float* xrow = x + (act ? b * 4096 + (long)i * 64 : 0);
        const float* b0s = (const float*)(smem + GS_B0);
        float acc[8];
#pragma unroll
        for (int o = 0; o < 8; o++) acc[o] = b0s[o];
#pragma unroll
        for (int half = 0; half < 2; half++) {
            float4 xr[8];
#pragma unroll
            for (int q = 0; q < 8; q++)
                xr[q] = act ? *(const float4*)&xrow[half * 32 + q * 4]
                            : make_float4(0.f, 0.f, 0.f, 0.f);
#pragma unroll
            for (int o = 0; o < 8; o++) {
#pragma unroll
                for (int q = 0; q < 8; q++) {
                    float4 wv = *(const float4*)&W0s[o * 64 + half * 32 + q * 4];
                    acc[o] = fmaf(xr[q].x, wv.x, fmaf(xr[q].y, wv.y,
                             fmaf(xr[q].z, wv.z, fmaf(xr[q].w, wv.w, acc[o]))));
                }
            }
        }
#pragma unroll
        for (int o = 0; o < 8; o++) {
            __nv_bfloat16 h, l;
            split_bf16(acc[o], h, l);
            *(__nv_bfloat16*)(smem + GS_CM_HI + (((s * 8 + o) * 72 + i) << 1)) = h;
            *(__nv_bfloat16*)(smem + GS_CM_LO + (((s * 8 + o) * 72 + i) << 1)) = l;
        }
    }
    cp_wait<0>();
    __syncthreads();

    const float* b1s = (const float*)(smem + GS_B1);
    const float* b2s = (const float*)(smem + GS_B2);
    const float* b3s = (const float*)(smem + GS_B3);
    long bbase = (long)blockIdx.x * 4;

    kmul_mma<8, true>(smem, sb, lane, w, 0);
    __syncthreads();

    kmul_mma<8, false>(smem, sb, lane, w, 1);
    __syncthreads();
    wmul_mma<8, 16, 1>(smem, sb, lane, w, b1s, bbase, B);
    __syncthreads();

    kmul_mma<16, false>(smem, sb, lane, w, 2);
    __syncthreads();
    wmul_mma<16, 32, 2>(smem, sb, lane, w, b2s, bbase, B);
    __syncthreads();

    kmul_mma<32, false>(smem, sb, lane, w, 3);
    __syncthreads();
    wmul_mma<32, 64, 3>(smem, sb, lane, w, b3s, bbase, B);
}

// ---------------------------------------------------------------------------
// Kernel C (HMMA): M=64 tile, 128 threads (4 warps = 2Mx2N of 32x40 tiles),
// double-buffered kc=64, 2 CTAs/SM, grid 256 (one wave).
// ---------------------------------------------------------------------------
#define C3_SW1    0
#define C3_STG0   19456
#define C3_A_HI   0
#define C3_A_LO   9216
#define C3_B_HI   18432
#define C3_B_LO   29952
#define C3_STG_SZ 41472
#define C3_SMEM   (C3_STG0 + 2 * C3_STG_SZ)        // 102400

__global__ __launch_bounds__(128, 2) void compress_mma_kernel(
    const float* __restrict__ bm0, const float* __restrict__ wm1,
    const float* __restrict__ bm1, float* __restrict__ out, int B) {
    extern __shared__ char smem[];
    uint32_t sb = smem_u32(smem);
    int tid = threadIdx.x;
    long m0 = (long)blockIdx.x * 64;

    int lane = tid & 31, w = tid >> 5;
    int mw = w >> 1, nw = w & 1;
    int g = lane >> 3;

    auto load_chunk = [&](int c, int bsel) {
        uint32_t stg = sb + C3_STG0 + bsel * C3_STG_SZ;
        int k0 = c * 64;
        for (int q = tid; q < 512; q += 128) {
            int m = q >> 3, kk = q & 7;
            long gm = m0 + m;
            int ok = (gm < B);
            size_t off = (size_t)(ok ? gm : 0) * 4096 + k0 + kk * 8;
            int sz = ok ? 16 : 0;
            uint32_t d = stg + m * 144 + kk * 16;
            cp16(d + C3_A_HI, g_hi + off, sz);
            cp16(d + C3_A_LO, g_lo + off, sz);
        }
        for (int q = tid; q < 640; q += 128) {
            int o = q >> 3, kk = q & 7;
            size_t off = (size_t)o * 4096 + k0 + kk * 8;
            uint32_t d = stg + o * 144 + kk * 16;
            cp16(d + C3_B_HI, g_w0hi + off, 16);
            cp16(d + C3_B_LO, g_w0lo + off, 16);
        }
        cp_commit();
    };

    load_chunk(0, 0);

    float* sW1 = (float*)(smem + C3_SW1);
    for (int t = tid; t < 4800; t += 128) sW1[t] = wm1[t];

    load_chunk(1, 1);

    float acc[2][5][4];
#pragma unroll
    for (int mt = 0; mt < 2; mt++)
#pragma unroll
        for (int nt = 0; nt < 5; nt++)
#pragma unroll
            for (int e = 0; e < 4; e++) acc[mt][nt][e] = 0.0f;

    // R8-verified fragment addressing (M=64: mw in {0,1})
    uint32_t aoff0 = (uint32_t)(mw * 32 + ((lane >> 3) & 1) * 8 + (lane & 7)) * 144
                     + (uint32_t)(lane >> 4) * 16;
    uint32_t boff0 = (uint32_t)(nw * 40 + (g >> 1) * 8 + (lane & 7)) * 144 + (uint32_t)(g & 1) * 16;
    uint32_t boff2 = (uint32_t)(nw * 40 + 32 + (lane & 7)) * 144 + (uint32_t)((lane >> 3) & 1) * 16;

#pragma unroll 1
    for (int c = 0; c < 64; c++) {
        int bsel = c & 1;
        cp_wait<1>();
        __syncthreads();
        uint32_t stg = sb + C3_STG0 + bsel * C3_STG_SZ;

#pragma unroll
        for (int ks = 0; ks < 4; ks++) {
            uint32_t ahi[2][4], alo[2][4], bhi[5][2], blo[5][2];
            uint32_t ao = stg + aoff0 + ks * 32;
            ldsm4(ahi[0], ao + C3_A_HI);
            ldsm4(ahi[1], ao + C3_A_HI + 16 * 144);
            ldsm4(alo[0], ao + C3_A_LO);
            ldsm4(alo[1], ao + C3_A_LO + 16 * 144);
            uint32_t bo = stg + boff0 + ks * 32;
            uint32_t bo2 = stg + boff2 + ks * 32;
            ldsm4(&bhi[0][0], bo + C3_B_HI);
            ldsm4(&bhi[2][0], bo + C3_B_HI + 16 * 144);
            ldsm2(&bhi[4][0], bo2 + C3_B_HI);
            ldsm4(&blo[0][0], bo + C3_B_LO);
            ldsm4(&blo[2][0], bo + C3_B_LO + 16 * 144);
            ldsm2(&blo[4][0], bo2 + C3_B_LO);
#pragma unroll
            for (int mt = 0; mt < 2; mt++)
#pragma unroll
                for (int nt = 0; nt < 5; nt++) {
                    mma16816(acc[mt][nt], ahi[mt], bhi[nt]);
                    mma16816(acc[mt][nt], alo[mt], bhi[nt]);
                    mma16816(acc[mt][nt], ahi[mt], blo[nt]);
                }
        }
        __syncthreads();
        if (c + 2 < 64) load_chunk(c + 2, bsel);
        else cp_commit();
    }

    // Epilogue: acc -> +bm0 -> lrelu -> h1[64][81] (overlays stage area)
    float* h1 = (float*)(smem + C3_STG0);
    int qrow = lane >> 2;
    int qcol = (lane & 3) * 2;
#pragma unroll
    for (int mt = 0; mt < 2; mt++)
#pragma unroll
        for (int i = 0; i < 2; i++) {
            int r = mw * 32 + mt * 16 + qrow + i * 8;
#pragma unroll
            for (int nt = 0; nt < 5; nt++)
#pragma unroll
                for (int j = 0; j < 2; j++) {
                    int col = nw * 40 + nt * 8 + qcol + j;
                    h1[r * 81 + col] = lrelu(acc[mt][nt][i * 2 + j] + __ldg(&bm0[col]));
                }
        }
    __syncthreads();

    // Second layer: 64 rows x 60 outs = 3840 outputs over 128 threads.
#pragma unroll 1
    for (int ii = 0; ii < 30; ii++) {
        int idx = tid + ii * 128;
        int m = idx & 63, o2 = idx >> 6;
        float a = __ldg(&bm1[o2]);
#pragma unroll 4
        for (int c4 = 0; c4 < 80; c4 += 4) {
            float4 wv = *(const float4*)&sW1[o2 * 80 + c4];
            a = fmaf(h1[m * 81 + c4 + 0], wv.x,
                fmaf(h1[m * 81 + c4 + 1], wv.y,
                fmaf(h1[m * 81 + c4 + 2], wv.z,
                fmaf(h1[m * 81 + c4 + 3], wv.w, a))));
        }
        long gm = m0 + m;
        if (gm < B) out[gm * 60 + o2] = lrelu(a);
    }
}

// ---------------------------------------------------------------------------
extern "C" void kernel_launch(void* const* d_in, const int* in_sizes, int n_in,
                              void* d_out, int out_size) {
    const float* x   = (const float*)d_in[0];
    const float* w0  = (const float*)d_in[1];
    const float* b0  = (const float*)d_in[2];
    const float* s0  = (const float*)d_in[3];
    const float* w1  = (const float*)d_in[4];
    const float* b1  = (const float*)d_in[5];
    const float* s1  = (const float*)d_in[6];
    const float* w2  = (const float*)d_in[7];
    const float* b2  = (const float*)d_in[8];
    const float* s2  = (const float*)d_in[9];
    const float* w3  = (const float*)d_in[10];
    const float* b3  = (const float*)d_in[11];
    const float* s3  = (const float*)d_in[12];
    const float* wm0 = (const float*)d_in[13];
    const float* bm0 = (const float*)d_in[14];
    const float* wm1 = (const float*)d_in[15];
    const float* bm1 = (const float*)d_in[16];

    int B = in_sizes[0] / 4096;
    if (B > MAXB) B = MAXB;

    cudaFuncSetAttribute((const void*)kprep2_kernel,
                         cudaFuncAttributeMaxDynamicSharedMemorySize, 65536);
    cudaFuncSetAttribute((const void*)gauss_mma_kernel,
                         cudaFuncAttributeMaxDynamicSharedMemorySize, GS_SMEM);
    cudaFuncSetAttribute((const void*)compress_mma_kernel,
                         cudaFuncAttributeMaxDynamicSharedMemorySize, C3_SMEM);

    kprep2_kernel<<<1, 256, 65536>>>(s0, s1, s2, s3);
    wprep2_kernel<<<160, 512>>>(wm0, w1, w2, w3);
    gauss_mma_kernel<<<(B + 3) / 4, 256, GS_SMEM>>>(x, w0, b0, b1, b2, b3, B);
    compress_mma_kernel<<<(B + 63) / 64, 128, C3_SMEM>>>(
        bm0, wm1, bm1, (float*)d_out, B);
}